// round 13
// baseline (speedup 1.0000x reference)
#include <cuda_runtime.h>
#include <cuda_fp16.h>
#include <cstdint>

#define NN 200000
#define EE 600000
#define GG 8192
#define HH 128
#define NB 196            // scan blocks: 196*1024 >= NN

// weight scratch offsets (floats)
#define WOFF_INW  0
#define WOFF_CONV 8192
#define WOFF_PW1  73728
#define WOFF_HW1  90112
#define WOFF_PW2T 122880
#define WTOT      139264

// ---------------- scratch (device globals: allocation-free) ----------------
__device__ __half g_h  [(size_t)NN*HH];     // residual stream (fp16 = tf32 mantissa)
__device__ __half g_hw [(size_t)NN*HH];     // conv outputs pre-scaled by dis (fp16)
__device__ float  g_dis[NN];
__device__ float  g_gsum[(size_t)GG*HH];
__device__ float  g_cnt[GG];
__device__ float  g_gh [(size_t)GG*HH];
__device__ float  g_wc  [HH*HH];
__device__ float  g_c2  [HH];
__device__ float  g_wr  [WTOT];             // tf32-rounded weights
// CSR
__device__ int g_deg[NN];
__device__ int g_fill[NN];
__device__ int g_rowptr[NN];
__device__ int g_csrc[EE];
__device__ int g_bsum[256];
__device__ int g_boff[256];

// ---------------- small helpers ----------------
__device__ __forceinline__ float4 ld4(const float* p){ return *reinterpret_cast<const float4*>(p); }
__device__ __forceinline__ float siluf(float x){ return x / (1.f + __expf(-x)); }
__device__ __forceinline__ uint32_t f2tf32(float f){
    uint32_t u;
    asm("cvt.rna.tf32.f32 %0, %1;" : "=r"(u) : "f"(f));
    return u;
}
__device__ __forceinline__ float tf32r(float f){ return __uint_as_float(f2tf32(f)); }
__device__ __forceinline__ uint32_t smem_u32(const void* p){
    uint32_t a;
    asm("{ .reg .u64 t; cvta.to.shared.u64 t, %1; cvt.u32.u64 %0, t; }" : "=r"(a) : "l"(p));
    return a;
}
__device__ __forceinline__ void cpa16(uint32_t sa, const void* gp, uint32_t sz){
    asm volatile("cp.async.cg.shared.global [%0], [%1], 16, %2;" :: "r"(sa), "l"(gp), "r"(sz));
}
__device__ __forceinline__ void mma1688(float* d, const uint32_t* a, const uint32_t* b){
    asm volatile("mma.sync.aligned.m16n8k8.row.col.f32.tf32.tf32.f32 "
        "{%0,%1,%2,%3}, {%4,%5,%6,%7}, {%8,%9}, {%0,%1,%2,%3};"
        : "+f"(d[0]), "+f"(d[1]), "+f"(d[2]), "+f"(d[3])
        : "r"(a[0]), "r"(a[1]), "r"(a[2]), "r"(a[3]), "r"(b[0]), "r"(b[1]));
}
__device__ __forceinline__ void acc8(float* a, uint4 u){
    float2 f;
    f = __half22float2(*reinterpret_cast<__half2*>(&u.x)); a[0]+=f.x; a[1]+=f.y;
    f = __half22float2(*reinterpret_cast<__half2*>(&u.y)); a[2]+=f.x; a[3]+=f.y;
    f = __half22float2(*reinterpret_cast<__half2*>(&u.z)); a[4]+=f.x; a[5]+=f.y;
    f = __half22float2(*reinterpret_cast<__half2*>(&u.w)); a[6]+=f.x; a[7]+=f.y;
}
__device__ __forceinline__ void unp8(float* a, uint4 u){
    float2 f;
    f = __half22float2(*reinterpret_cast<__half2*>(&u.x)); a[0]=f.x; a[1]=f.y;
    f = __half22float2(*reinterpret_cast<__half2*>(&u.y)); a[2]=f.x; a[3]=f.y;
    f = __half22float2(*reinterpret_cast<__half2*>(&u.z)); a[4]=f.x; a[5]=f.y;
    f = __half22float2(*reinterpret_cast<__half2*>(&u.w)); a[6]=f.x; a[7]=f.y;
}
__device__ __forceinline__ uint4 pk8(const float* v){
    uint4 u;
    *reinterpret_cast<__half2*>(&u.x) = __floats2half2_rn(v[0], v[1]);
    *reinterpret_cast<__half2*>(&u.y) = __floats2half2_rn(v[2], v[3]);
    *reinterpret_cast<__half2*>(&u.z) = __floats2half2_rn(v[4], v[5]);
    *reinterpret_cast<__half2*>(&u.w) = __floats2half2_rn(v[6], v[7]);
    return u;
}

// ---------------- init (deg/fill zero, out=b2, pool zero) ----------------
__global__ void init_k(float* __restrict__ out, const float* __restrict__ b2){
    int i = blockIdx.x*blockDim.x + threadIdx.x;
    if (i < NN) { g_deg[i] = 0; g_fill[i] = 0; out[i] = b2[0]; }
    if (i < GG*HH) g_gsum[i] = 0.f;
    if (i < GG)    g_cnt[i]  = 0.f;
}

// ---------------- CSR build ----------------
__global__ void csr_hist_k(const int* __restrict__ dst){
    int e = blockIdx.x*blockDim.x + threadIdx.x;
    if (e < EE) atomicAdd(&g_deg[dst[e]], 1);
}
__global__ __launch_bounds__(256) void csr_scan1_k(){
    __shared__ int ss[256];
    const int tid = threadIdx.x;
    const int i0  = blockIdx.x*1024 + tid*4;
    int v[4];
#pragma unroll
    for (int q = 0; q < 4; q++) v[q] = (i0+q < NN) ? g_deg[i0+q] : 0;
    int tsum = v[0]+v[1]+v[2]+v[3];
    ss[tid] = tsum; __syncthreads();
#pragma unroll
    for (int off = 1; off < 256; off <<= 1) {
        int t = (tid >= off) ? ss[tid-off] : 0;
        __syncthreads();
        ss[tid] += t;
        __syncthreads();
    }
    if (tid == 255) g_bsum[blockIdx.x] = ss[255];
    int run = ss[tid] - tsum;
#pragma unroll
    for (int q = 0; q < 4; q++) {
        if (i0+q < NN) { g_rowptr[i0+q] = run; run += v[q]; }
    }
}
__global__ __launch_bounds__(256) void csr_scan2_k(){
    __shared__ int ss[256];
    const int tid = threadIdx.x;
    int v = (tid < NB) ? g_bsum[tid] : 0;
    ss[tid] = v; __syncthreads();
#pragma unroll
    for (int off = 1; off < 256; off <<= 1) {
        int t = (tid >= off) ? ss[tid-off] : 0;
        __syncthreads();
        ss[tid] += t;
        __syncthreads();
    }
    if (tid < NB) g_boff[tid] = ss[tid] - v;   // exclusive
}
__global__ void csr_scan3_k(){
    int i = blockIdx.x*blockDim.x + threadIdx.x;
    if (i < NN) {
        g_rowptr[i] += g_boff[i >> 10];
        g_dis[i] = rsqrtf((float)g_deg[i] + 1.0f);
    }
}
__global__ void csr_fill_k(const int* __restrict__ src, const int* __restrict__ dst){
    int e = blockIdx.x*blockDim.x + threadIdx.x;
    if (e < EE) {
        int d = dst[e];
        int pos = g_rowptr[d] + atomicAdd(&g_fill[d], 1);
        g_csrc[pos] = src[e];
    }
}

// ---------------- weight prep: tf32-round all GEMM weights ------------------
__global__ void prep_w_k(const float* __restrict__ in_w, const float* __restrict__ conv_w,
                         const float* __restrict__ pw1, const float* __restrict__ hw1,
                         const float* __restrict__ pw2){
    int i = blockIdx.x*blockDim.x + threadIdx.x;
    if (i < 8192)        g_wr[WOFF_INW  + i] = tf32r(in_w[i]);
    else if (i < 73728)  { int j = i-8192;   g_wr[WOFF_CONV + j] = tf32r(conv_w[j]); }
    else if (i < 90112)  { int j = i-73728;  g_wr[WOFF_PW1  + j] = tf32r(pw1[j]); }
    else if (i < 122880) { int j = i-90112;  g_wr[WOFF_HW1  + j] = tf32r(hw1[j]); }
    else if (i < WTOT)   { int j = i-122880; int r = j>>7, c = j&127;
                           g_wr[WOFF_PW2T + c*HH + r] = tf32r(pw2[j]); }
}
__global__ void c2_k(const float* __restrict__ hw1, const float* __restrict__ pb2,
                     const float* __restrict__ hb1){
    int i = threadIdx.x;
    float s = 0.f;
    for (int k = 0; k < HH; k++) s = fmaf(hw1[i*256 + k], pb2[k], s);
    g_c2[i] = s + hb1[i];
}

// ---------------- TF32 tensor-core GEMM (cp.async 2-stage pipeline) ----------
// out[M,128] = A[M,KT] @ W[128,KT]^T  (A row stride lda elems, W row stride ldw)
// EPI 0: out = acc (+bias) ; EPI 1: conv (out_h = half(acc*dis[row])) ;
// EPI 3: out = acc / max(g_cnt[row],1)  (pool mean fold)
// AH: A fp16 ; CVTA: A raw fp32 -> tf32 in-fragment ; ROUND: tf32-round fp32 out
template<int KT, int EPI, bool OUTH, bool AH, bool CVTA, bool ROUND>
__global__ __launch_bounds__(256, 2) void mma_gemm_k(
    const void* __restrict__ Av, int lda,
    const float* __restrict__ W, int ldw, const float* __restrict__ bias,
    void* __restrict__ outv, int M)
{
    constexpr int KC = 32, NC = KT / KC;
    constexpr int LDSW = 36;
    constexpr int LDSA = AH ? 40 : 36;
    constexpr int ABYTES = 128 * LDSA * (AH ? 2 : 4);
    constexpr int WBYTES = 128 * LDSW * 4;
    extern __shared__ char smem[];

    const int tid = threadIdx.x, wid = tid >> 5, lid = tid & 31;
    const int wm = wid & 3, wn = wid >> 2;
    const int g  = lid >> 2, t = lid & 3;
    const int brow = blockIdx.x * 128;

    float acc[2][8][4];
#pragma unroll
    for (int mt = 0; mt < 2; mt++)
#pragma unroll
        for (int nt = 0; nt < 8; nt++)
#pragma unroll
            for (int q = 0; q < 4; q++) acc[mt][nt][q] = 0.f;

#define ISSUE(ci) do {                                                          \
        int _st = (ci) & 1;                                                     \
        char* Ad = smem + _st*ABYTES;                                           \
        char* Wd = smem + 2*ABYTES + _st*WBYTES;                                \
        if (AH) {                                                               \
            const __half* Ag = (const __half*)Av;                               \
            _Pragma("unroll")                                                   \
            for (int f = tid; f < 512; f += 256) {                              \
                int row = f >> 2, kq = (f & 3) * 8;                             \
                int gr = brow + row;                                            \
                cpa16(smem_u32(Ad + (row*LDSA + kq)*2),                         \
                      Ag + (size_t)gr*lda + (ci)*KC + kq, (gr < M) ? 16u : 0u); \
            }                                                                   \
        } else {                                                                \
            const float* Ag = (const float*)Av;                                 \
            _Pragma("unroll")                                                   \
            for (int f = tid; f < 1024; f += 256) {                             \
                int row = f >> 3, kq = (f & 7) * 4;                             \
                int gr = brow + row;                                            \
                cpa16(smem_u32(Ad + (row*LDSA + kq)*4),                         \
                      Ag + (size_t)gr*lda + (ci)*KC + kq, (gr < M) ? 16u : 0u); \
            }                                                                   \
        }                                                                       \
        _Pragma("unroll")                                                       \
        for (int f = tid; f < 1024; f += 256) {                                 \
            int n = f >> 3, kq = (f & 7) * 4;                                   \
            cpa16(smem_u32(Wd + (n*LDSW + kq)*4),                               \
                  W + (size_t)n*ldw + (ci)*KC + kq, 16u);                       \
        }                                                                       \
        asm volatile("cp.async.commit_group;");                                 \
    } while(0)

    ISSUE(0);
#pragma unroll
    for (int ci = 0; ci < NC; ci++) {
        if (ci + 1 < NC) { ISSUE(ci + 1); asm volatile("cp.async.wait_group 1;"); }
        else             { asm volatile("cp.async.wait_group 0;"); }
        __syncthreads();
        const char* Ab = smem + (ci & 1)*ABYTES;
        const float* Ws = (const float*)(smem + 2*ABYTES + (ci & 1)*WBYTES);
#pragma unroll
        for (int ks = 0; ks < KC/8; ks++) {
            const int kk = ks*8;
            uint32_t a[2][4], b[8][2];
#pragma unroll
            for (int mt = 0; mt < 2; mt++) {
                if (AH) {
                    const __half* ap = (const __half*)Ab + (wm*32 + mt*16 + g)*LDSA + kk + t;
                    a[mt][0] = __float_as_uint(__half2float(ap[0]));
                    a[mt][1] = __float_as_uint(__half2float(ap[8*LDSA]));
                    a[mt][2] = __float_as_uint(__half2float(ap[4]));
                    a[mt][3] = __float_as_uint(__half2float(ap[8*LDSA + 4]));
                } else {
                    const float* ap = (const float*)Ab + (wm*32 + mt*16 + g)*LDSA + kk + t;
                    a[mt][0] = __float_as_uint(ap[0]);
                    a[mt][1] = __float_as_uint(ap[8*LDSA]);
                    a[mt][2] = __float_as_uint(ap[4]);
                    a[mt][3] = __float_as_uint(ap[8*LDSA + 4]);
                    if (CVTA) {
#pragma unroll
                        for (int q = 0; q < 4; q++) a[mt][q] = f2tf32(__uint_as_float(a[mt][q]));
                    }
                }
            }
#pragma unroll
            for (int nt = 0; nt < 8; nt++) {
                const float* bp = Ws + (wn*64 + nt*8 + g)*LDSW + kk + t;
                b[nt][0] = __float_as_uint(bp[0]);
                b[nt][1] = __float_as_uint(bp[4]);
            }
#pragma unroll
            for (int mt = 0; mt < 2; mt++)
#pragma unroll
                for (int nt = 0; nt < 8; nt++)
                    mma1688(acc[mt][nt], a[mt], b[nt]);
        }
        __syncthreads();
    }
#undef ISSUE

    float*  outf = (float*) outv;
    __half* outh = (__half*)outv;
#pragma unroll
    for (int mt = 0; mt < 2; mt++) {
#pragma unroll
        for (int half = 0; half < 2; half++) {
            int row = brow + wm*32 + mt*16 + g + half*8;
            if (row >= M) continue;
            size_t ro = (size_t)row*HH;
            float dsc = 0.f;
            if (EPI == 1) dsc = g_dis[row];
            if (EPI == 3) dsc = 1.f / fmaxf(g_cnt[row], 1.f);
#pragma unroll
            for (int nt = 0; nt < 8; nt++) {
                int col = wn*64 + nt*8 + t*2;
                float v0 = acc[mt][nt][half*2 + 0];
                float v1 = acc[mt][nt][half*2 + 1];
                if (EPI == 0) {
                    if (bias) { v0 += bias[col]; v1 += bias[col+1]; }
                } else if (EPI == 1 || EPI == 3) {
                    v0 *= dsc; v1 *= dsc;
                }
                if (ROUND) { v0 = tf32r(v0); v1 = tf32r(v1); }
                if (OUTH) {
                    *reinterpret_cast<__half2*>(outh + ro + col) = __floats2half2_rn(v0, v1);
                } else {
                    *reinterpret_cast<float2*>(outf + ro + col) = make_float2(v0, v1);
                }
            }
        }
    }
}

// ---------------- fused head GEMM ---------------------------------------------
// phase 1: t1 = silu(h @ pw1^T + pb1)           (kept in smem, fp16)
// phase 2: acc = h @ W1a_h^T + t1 @ Wc^T
// epilogue: hid = silu(acc + c2 + gh[batch]) ; out[row] += hid . w2
__global__ __launch_bounds__(256, 2) void head_gemm_k(
    const float* __restrict__ w2, const int* __restrict__ batch,
    const float* __restrict__ pb1, float* __restrict__ out)
{
    constexpr int KC = 32;
    constexpr int LDSW = 36, LDSA = 40, T1LD = 136;
    constexpr int ABYTES = 128 * LDSA * 2;     // 10240
    constexpr int WBYTES = 128 * LDSW * 4;     // 18432
    extern __shared__ char smem[];
    __half* t1s = (__half*)(smem + 2*ABYTES + 2*WBYTES);   // 128*136*2 = 34816

    const int tid = threadIdx.x, wid = tid >> 5, lid = tid & 31;
    const int wm = wid & 3, wn = wid >> 2;
    const int g  = lid >> 2, t = lid & 3;
    const int brow = blockIdx.x * 128;

    float acc[2][8][4];
#pragma unroll
    for (int mt = 0; mt < 2; mt++)
#pragma unroll
        for (int nt = 0; nt < 8; nt++)
#pragma unroll
            for (int q = 0; q < 4; q++) acc[mt][nt][q] = 0.f;

    // A loader (g_h, fp16) + W loader
#define HA_LOAD(ci) do {                                                        \
        char* Ad = smem + ((ci) & 1)*ABYTES;                                    \
        _Pragma("unroll")                                                       \
        for (int f = tid; f < 512; f += 256) {                                  \
            int row = f >> 2, kq = (f & 3) * 8;                                 \
            int gr = brow + row;                                                \
            cpa16(smem_u32(Ad + (row*LDSA + kq)*2),                             \
                  g_h + (size_t)gr*HH + (((ci)*KC) & 127) + kq,                 \
                  (gr < NN) ? 16u : 0u);                                        \
        } } while(0)
#define HW_LOAD(ci, WP, LDWV, KOFF) do {                                        \
        char* Wd = smem + 2*ABYTES + ((ci) & 1)*WBYTES;                         \
        _Pragma("unroll")                                                       \
        for (int f = tid; f < 1024; f += 256) {                                 \
            int n = f >> 3, kq = (f & 7) * 4;                                   \
            cpa16(smem_u32(Wd + (n*LDSW + kq)*4),                               \
                  (WP) + (size_t)n*(LDWV) + (KOFF) + kq, 16u);                  \
        } } while(0)
#define HCOMPUTE(ci, FROM_T1, T1OFF)                                            \
        { __syncthreads();                                                      \
          const __half* As = (const __half*)(smem + ((ci) & 1)*ABYTES);         \
          const float*  Ws = (const float*)(smem + 2*ABYTES + ((ci) & 1)*WBYTES); \
          _Pragma("unroll")                                                     \
          for (int ks = 0; ks < KC/8; ks++) {                                   \
              const int kk = ks*8;                                              \
              uint32_t a[2][4], b[8][2];                                        \
              _Pragma("unroll")                                                 \
              for (int mt = 0; mt < 2; mt++) {                                  \
                  const __half* ap = FROM_T1                                    \
                      ? t1s + (wm*32 + mt*16 + g)*T1LD + (T1OFF) + kk + t       \
                      : As + (wm*32 + mt*16 + g)*LDSA + kk + t;                 \
                  const int rstep = FROM_T1 ? 8*T1LD : 8*LDSA;                  \
                  a[mt][0] = __float_as_uint(__half2float(ap[0]));              \
                  a[mt][1] = __float_as_uint(__half2float(ap[rstep]));          \
                  a[mt][2] = __float_as_uint(__half2float(ap[4]));              \
                  a[mt][3] = __float_as_uint(__half2float(ap[rstep + 4]));      \
              }                                                                 \
              _Pragma("unroll")                                                 \
              for (int nt = 0; nt < 8; nt++) {                                  \
                  const float* bp = Ws + (wn*64 + nt*8 + g)*LDSW + kk + t;      \
                  b[nt][0] = __float_as_uint(bp[0]);                            \
                  b[nt][1] = __float_as_uint(bp[4]);                            \
              }                                                                 \
              _Pragma("unroll")                                                 \
              for (int mt = 0; mt < 2; mt++)                                    \
                  _Pragma("unroll")                                             \
                  for (int nt = 0; nt < 8; nt++)                                \
                      mma1688(acc[mt][nt], a[mt], b[nt]);                       \
          }                                                                     \
          __syncthreads(); }

    // ---- phase 1: acc = h @ pw1^T ----
    const float* PW1 = g_wr + WOFF_PW1;
    HA_LOAD(0); HW_LOAD(0, PW1, 128, 0);
    asm volatile("cp.async.commit_group;");
#pragma unroll
    for (int ci = 0; ci < 4; ci++) {
        if (ci + 1 < 4) {
            HA_LOAD(ci+1); HW_LOAD(ci+1, PW1, 128, (ci+1)*KC);
            asm volatile("cp.async.commit_group;");
            asm volatile("cp.async.wait_group 1;");
        } else asm volatile("cp.async.wait_group 0;");
        HCOMPUTE(ci, false, 0)
    }

    // phase-1 epilogue -> t1s (fp16), then reset acc
#pragma unroll
    for (int mt = 0; mt < 2; mt++)
#pragma unroll
        for (int half = 0; half < 2; half++) {
            int m = wm*32 + mt*16 + g + half*8;
#pragma unroll
            for (int nt = 0; nt < 8; nt++) {
                int col = wn*64 + nt*8 + t*2;
                float v0 = siluf(acc[mt][nt][half*2+0] + pb1[col]);
                float v1 = siluf(acc[mt][nt][half*2+1] + pb1[col+1]);
                *reinterpret_cast<__half2*>(t1s + m*T1LD + col) = __floats2half2_rn(v0, v1);
            }
        }
#pragma unroll
    for (int mt = 0; mt < 2; mt++)
#pragma unroll
        for (int nt = 0; nt < 8; nt++)
#pragma unroll
            for (int q = 0; q < 4; q++) acc[mt][nt][q] = 0.f;
    __syncthreads();

    // ---- phase 2: acc = h @ W1a^T + t1 @ Wc^T (K=256) ----
    const float* W1A = g_wr + WOFF_HW1;
    HA_LOAD(0); HW_LOAD(0, W1A, 256, 0);
    asm volatile("cp.async.commit_group;");
#pragma unroll
    for (int ci = 0; ci < 8; ci++) {
        if (ci + 1 < 8) {
            if (ci + 1 < 4) { HA_LOAD(ci+1); HW_LOAD(ci+1, W1A, 256, (ci+1)*KC); }
            else            { HW_LOAD(ci+1, g_wc, 128, ((ci+1)-4)*KC); }
            asm volatile("cp.async.commit_group;");
            asm volatile("cp.async.wait_group 1;");
        } else asm volatile("cp.async.wait_group 0;");
        if (ci < 4) HCOMPUTE(ci, false, 0)
        else        HCOMPUTE(ci, true, (ci-4)*KC)
    }
#undef HA_LOAD
#undef HW_LOAD
#undef HCOMPUTE

    // ---- final epilogue: silu + dot(w2) + red.add ----
#pragma unroll
    for (int mt = 0; mt < 2; mt++) {
#pragma unroll
        for (int half = 0; half < 2; half++) {
            int row = brow + wm*32 + mt*16 + g + half*8;
            float partial = 0.f;
            if (row < NN) {
                const float* ghrow = g_gh + (size_t)batch[row]*HH;
#pragma unroll
                for (int nt = 0; nt < 8; nt++) {
                    int col = wn*64 + nt*8 + t*2;
                    float v0 = siluf(acc[mt][nt][half*2+0] + g_c2[col]   + ghrow[col]);
                    float v1 = siluf(acc[mt][nt][half*2+1] + g_c2[col+1] + ghrow[col+1]);
                    partial = fmaf(v0, w2[col], partial);
                    partial = fmaf(v1, w2[col+1], partial);
                }
            }
            partial += __shfl_xor_sync(0xffffffffu, partial, 1);
            partial += __shfl_xor_sync(0xffffffffu, partial, 2);
            if (t == 0 && row < NN)
                asm volatile("red.global.add.f32 [%0], %1;" :: "l"(out + row), "f"(partial) : "memory");
        }
    }
}

// ---- fused neighbor-gather + silu + LN + residual (+pool) ------------------
// half-warp (16 lanes) per node, 16B fp16 loads; batched 4-wide neighbor loads.
template<bool POOL>
__global__ __launch_bounds__(256) void gather_ln_k(const float* __restrict__ bias,
                                                   const float* __restrict__ lng,
                                                   const float* __restrict__ lnb,
                                                   const int* __restrict__ batch)
{
    int node = blockIdx.x * 16 + (threadIdx.x >> 4);
    if (node >= NN) return;
    const int l16 = threadIdx.x & 15;
    const int c0  = l16 * 8;
    const int cnt   = g_deg[node];
    const int start = g_rowptr[node];
    const float di  = g_dis[node];
    const size_t off = (size_t)node*HH + c0;

    float a[8] = {0,0,0,0,0,0,0,0};
    acc8(a, *reinterpret_cast<const uint4*>(g_hw + off));   // self term (already *di)

    for (int base = 0; base < cnt; base += 4) {
        int m = cnt - base;
        int i0 = g_csrc[start + base];
        int i1 = (m > 1) ? g_csrc[start + base + 1] : i0;
        int i2 = (m > 2) ? g_csrc[start + base + 2] : i0;
        int i3 = (m > 3) ? g_csrc[start + base + 3] : i0;
        uint4 u0 = *reinterpret_cast<const uint4*>(g_hw + (size_t)i0*HH + c0);
        uint4 u1 = *reinterpret_cast<const uint4*>(g_hw + (size_t)i1*HH + c0);
        uint4 u2 = *reinterpret_cast<const uint4*>(g_hw + (size_t)i2*HH + c0);
        uint4 u3 = *reinterpret_cast<const uint4*>(g_hw + (size_t)i3*HH + c0);
        acc8(a, u0);
        if (m > 1) acc8(a, u1);
        if (m > 2) acc8(a, u2);
        if (m > 3) acc8(a, u3);
    }

    float4 b0 = ld4(bias + c0), b1 = ld4(bias + c0 + 4);
    float s[8];
    s[0] = siluf(fmaf(a[0], di, b0.x)); s[1] = siluf(fmaf(a[1], di, b0.y));
    s[2] = siluf(fmaf(a[2], di, b0.z)); s[3] = siluf(fmaf(a[3], di, b0.w));
    s[4] = siluf(fmaf(a[4], di, b1.x)); s[5] = siluf(fmaf(a[5], di, b1.y));
    s[6] = siluf(fmaf(a[6], di, b1.z)); s[7] = siluf(fmaf(a[7], di, b1.w));

    float sum = 0.f, sq = 0.f;
#pragma unroll
    for (int q = 0; q < 8; q++) { sum += s[q]; sq = fmaf(s[q], s[q], sq); }
#pragma unroll
    for (int o = 1; o < 16; o <<= 1) {
        sum += __shfl_xor_sync(0xffffffffu, sum, o);
        sq  += __shfl_xor_sync(0xffffffffu, sq,  o);
    }
    float mu  = sum * (1.f/128.f);
    float var = sq * (1.f/128.f) - mu*mu;
    float inv = rsqrtf(var + 1e-5f);

    float4 g0 = ld4(lng + c0), g1 = ld4(lng + c0 + 4);
    float4 e0 = ld4(lnb + c0), e1 = ld4(lnb + c0 + 4);
    float hv[8];
    unp8(hv, *reinterpret_cast<const uint4*>(g_h + off));
    hv[0] += (s[0]-mu)*inv*g0.x + e0.x;
    hv[1] += (s[1]-mu)*inv*g0.y + e0.y;
    hv[2] += (s[2]-mu)*inv*g0.z + e0.z;
    hv[3] += (s[3]-mu)*inv*g0.w + e0.w;
    hv[4] += (s[4]-mu)*inv*g1.x + e1.x;
    hv[5] += (s[5]-mu)*inv*g1.y + e1.y;
    hv[6] += (s[6]-mu)*inv*g1.z + e1.z;
    hv[7] += (s[7]-mu)*inv*g1.w + e1.w;
    *reinterpret_cast<uint4*>(g_h + off) = pk8(hv);

    if (POOL) {
        int b = batch[node];
        float* p = g_gsum + (size_t)b*HH + c0;
        asm volatile("red.global.add.v4.f32 [%0], {%1,%2,%3,%4};"
                     :: "l"(p), "f"(hv[0]), "f"(hv[1]), "f"(hv[2]), "f"(hv[3]) : "memory");
        asm volatile("red.global.add.v4.f32 [%0], {%1,%2,%3,%4};"
                     :: "l"(p+4), "f"(hv[4]), "f"(hv[5]), "f"(hv[6]), "f"(hv[7]) : "memory");
        if (l16 == 0) atomicAdd(&g_cnt[b], 1.0f);
    }
}

// ---------------- launch ----------------
extern "C" void kernel_launch(void* const* d_in, const int* in_sizes, int n_in,
                              void* d_out, int out_size)
{
    const float* x      = (const float*)d_in[0];
    const int*   ei     = (const int*)  d_in[1];
    const int*   src    = ei;
    const int*   dst    = ei + EE;
    const int*   batch  = (const int*)  d_in[2];
    const float* in_w   = (const float*)d_in[3];
    const float* in_b   = (const float*)d_in[4];
    const float* conv_w = (const float*)d_in[5];
    const float* conv_b = (const float*)d_in[6];
    const float* ln_g   = (const float*)d_in[7];
    const float* ln_b   = (const float*)d_in[8];
    const float* pw1    = (const float*)d_in[9];
    const float* pb1    = (const float*)d_in[10];
    const float* pw2    = (const float*)d_in[11];
    const float* pb2    = (const float*)d_in[12];
    const float* hw1    = (const float*)d_in[13];
    const float* hb1    = (const float*)d_in[14];
    const float* hw2    = (const float*)d_in[15];
    const float* hb2    = (const float*)d_in[16];
    float* out = (float*)d_out;

    float *p_gsum, *p_gh, *p_wc, *p_wr;
    __half *p_h, *p_hw;
    cudaGetSymbolAddress((void**)&p_h,    g_h);
    cudaGetSymbolAddress((void**)&p_hw,   g_hw);
    cudaGetSymbolAddress((void**)&p_gsum, g_gsum);
    cudaGetSymbolAddress((void**)&p_gh,   g_gh);
    cudaGetSymbolAddress((void**)&p_wc,   g_wc);
    cudaGetSymbolAddress((void**)&p_wr,   g_wr);

    // one-time host resources for fork/join graph parallelism
    static cudaStream_t s_csr = nullptr, s_wp = nullptr;
    static cudaEvent_t  ev_fork = nullptr, ev_csr = nullptr, ev_wp = nullptr;
    if (s_csr == nullptr) {
        cudaStreamCreateWithFlags(&s_csr, cudaStreamNonBlocking);
        cudaStreamCreateWithFlags(&s_wp,  cudaStreamNonBlocking);
        cudaEventCreateWithFlags(&ev_fork, cudaEventDisableTiming);
        cudaEventCreateWithFlags(&ev_csr,  cudaEventDisableTiming);
        cudaEventCreateWithFlags(&ev_wp,   cudaEventDisableTiming);
    }

    const int TPB = 256;
    const int gI  = (GG*HH + TPB - 1) / TPB;     // covers NN too
    const int gN  = (NN + TPB - 1) / TPB;
    const int gE  = (EE + TPB - 1) / TPB;
    const int gG16 = (NN + 15) / 16;
    const int gGm = (NN + 127) / 128;
    const int gGg = GG / 128;
    const int gW  = (WTOT + TPB - 1) / TPB;

    const int SMB_F = 4 * 128 * 36 * 4;              // 73728 (fp32 A)
    const int SMB_H = 2*128*40*2 + 2*128*36*4;       // 57344 (fp16 A)
    const int SMB_HEAD = SMB_H + 128*136*2;          // 92160
    cudaFuncSetAttribute(mma_gemm_k<128,0,false,false,false,true >, cudaFuncAttributeMaxDynamicSharedMemorySize, SMB_F);
    cudaFuncSetAttribute(mma_gemm_k< 64,0,true ,false,true ,false>, cudaFuncAttributeMaxDynamicSharedMemorySize, SMB_F);
    cudaFuncSetAttribute(mma_gemm_k<128,1,true ,true ,false,false>, cudaFuncAttributeMaxDynamicSharedMemorySize, SMB_H);
    cudaFuncSetAttribute(mma_gemm_k<128,3,false,false,true ,false>, cudaFuncAttributeMaxDynamicSharedMemorySize, SMB_F);
    cudaFuncSetAttribute(head_gemm_k, cudaFuncAttributeMaxDynamicSharedMemorySize, SMB_HEAD);

    // ---- init, then fork: CSR chain || weight-prep + in-proj ----
    init_k<<<gI, TPB>>>(out, hb2);
    cudaEventRecord(ev_fork, 0);
    cudaStreamWaitEvent(s_csr, ev_fork, 0);
    cudaStreamWaitEvent(s_wp,  ev_fork, 0);

    csr_hist_k <<<gE, TPB, 0, s_csr>>>(dst);
    csr_scan1_k<<<NB, TPB, 0, s_csr>>>();
    csr_scan2_k<<<1,  TPB, 0, s_csr>>>();
    csr_scan3_k<<<gN, TPB, 0, s_csr>>>();
    csr_fill_k <<<gE, TPB, 0, s_csr>>>(src, dst);
    cudaEventRecord(ev_csr, s_csr);

    prep_w_k<<<gW, TPB, 0, s_wp>>>(in_w, conv_w, pw1, hw1, pw2);
    c2_k<<<1, 128, 0, s_wp>>>(hw1, pb2, hb1);
    mma_gemm_k<128,0,false,false,false,true><<<1, TPB, SMB_F, s_wp>>>(
        p_wr + WOFF_HW1, 256, p_wr + WOFF_PW2T, 128, nullptr, p_wc, 128);
    mma_gemm_k<64,0,true,false,true,false><<<gGm, TPB, SMB_F, s_wp>>>(
        x, 64, p_wr + WOFF_INW, 64, in_b, p_h, NN);
    cudaEventRecord(ev_wp, s_wp);

    cudaStreamWaitEvent(0, ev_csr, 0);
    cudaStreamWaitEvent(0, ev_wp, 0);

    // ---- GCN layers ----
    for (int l = 0; l < 4; l++) {
        mma_gemm_k<128,1,true,true,false,false><<<gGm, TPB, SMB_H>>>(
            p_h, 128, p_wr + WOFF_CONV + (size_t)l*HH*HH, 128, nullptr, p_hw, NN);
        if (l < 3) gather_ln_k<false><<<gG16, TPB>>>(conv_b + l*HH, ln_g + l*HH, ln_b + l*HH, batch);
        else       gather_ln_k<true ><<<gG16, TPB>>>(conv_b + l*HH, ln_g + l*HH, ln_b + l*HH, batch);
    }

    // gh = (gsum/cnt) @ W1b.T
    mma_gemm_k<128,3,false,false,true,false><<<gGg, TPB, SMB_F>>>(
        p_gsum, 128, p_wr + WOFF_HW1 + 128, 256, nullptr, p_gh, GG);

    // fused head (t1 computed in-kernel)
    head_gemm_k<<<gGm, TPB, SMB_HEAD>>>(hw2, batch, pb1, out);
}

// round 14
// speedup vs baseline: 1.1225x; 1.1225x over previous
#include <cuda_runtime.h>
#include <cuda_fp16.h>
#include <cstdint>

#define NN 200000
#define EE 600000
#define GG 8192
#define HH 128
#define NB 196            // scan blocks: 196*1024 >= NN

// fp32 (tf32-rounded) weight scratch offsets (floats)
#define WOFF_INW  0
#define WOFF_HW1  8192
#define WOFF_PW2T 40960
#define WTOT      57344
// fp16 weight scratch offsets (halves)
#define HOFF_CONV 0
#define HOFF_PW1  65536
#define HOFF_W1A  81920
#define HTOT      98304

// ---------------- scratch (device globals: allocation-free) ----------------
__device__ __half g_h  [(size_t)NN*HH];     // residual stream (fp16)
__device__ __half g_hw [(size_t)NN*HH];     // conv outputs pre-scaled by dis (fp16)
__device__ float  g_dis[NN];
__device__ float  g_gsum[(size_t)GG*HH];
__device__ float  g_cnt[GG];
__device__ float  g_gh [(size_t)GG*HH];
__device__ __half g_wch[HH*HH];             // Wc (fp16)
__device__ float  g_c2  [HH];
__device__ float  g_wr  [WTOT];             // tf32-rounded fp32 weights
__device__ __half g_wh  [HTOT];             // fp16 weights (conv, pw1, w1a)
// CSR
__device__ int g_deg[NN];
__device__ int g_fill[NN];
__device__ int g_rowptr[NN];
__device__ int g_csrc[EE];
__device__ int g_bsum[256];
__device__ int g_boff[256];

// ---------------- small helpers ----------------
__device__ __forceinline__ float4 ld4(const float* p){ return *reinterpret_cast<const float4*>(p); }
__device__ __forceinline__ float siluf(float x){ return x / (1.f + __expf(-x)); }
__device__ __forceinline__ uint32_t f2tf32(float f){
    uint32_t u;
    asm("cvt.rna.tf32.f32 %0, %1;" : "=r"(u) : "f"(f));
    return u;
}
__device__ __forceinline__ float tf32r(float f){ return __uint_as_float(f2tf32(f)); }
__device__ __forceinline__ uint32_t smem_u32(const void* p){
    uint32_t a;
    asm("{ .reg .u64 t; cvta.to.shared.u64 t, %1; cvt.u32.u64 %0, t; }" : "=r"(a) : "l"(p));
    return a;
}
__device__ __forceinline__ void cpa16(uint32_t sa, const void* gp, uint32_t sz){
    asm volatile("cp.async.cg.shared.global [%0], [%1], 16, %2;" :: "r"(sa), "l"(gp), "r"(sz));
}
__device__ __forceinline__ void mma1688(float* d, const uint32_t* a, const uint32_t* b){
    asm volatile("mma.sync.aligned.m16n8k8.row.col.f32.tf32.tf32.f32 "
        "{%0,%1,%2,%3}, {%4,%5,%6,%7}, {%8,%9}, {%0,%1,%2,%3};"
        : "+f"(d[0]), "+f"(d[1]), "+f"(d[2]), "+f"(d[3])
        : "r"(a[0]), "r"(a[1]), "r"(a[2]), "r"(a[3]), "r"(b[0]), "r"(b[1]));
}
__device__ __forceinline__ void mma16816(float* d, const uint32_t* a, const uint32_t* b){
    asm volatile("mma.sync.aligned.m16n8k16.row.col.f32.f16.f16.f32 "
        "{%0,%1,%2,%3}, {%4,%5,%6,%7}, {%8,%9}, {%0,%1,%2,%3};"
        : "+f"(d[0]), "+f"(d[1]), "+f"(d[2]), "+f"(d[3])
        : "r"(a[0]), "r"(a[1]), "r"(a[2]), "r"(a[3]), "r"(b[0]), "r"(b[1]));
}
__device__ __forceinline__ void acc8(float* a, uint4 u){
    float2 f;
    f = __half22float2(*reinterpret_cast<__half2*>(&u.x)); a[0]+=f.x; a[1]+=f.y;
    f = __half22float2(*reinterpret_cast<__half2*>(&u.y)); a[2]+=f.x; a[3]+=f.y;
    f = __half22float2(*reinterpret_cast<__half2*>(&u.z)); a[4]+=f.x; a[5]+=f.y;
    f = __half22float2(*reinterpret_cast<__half2*>(&u.w)); a[6]+=f.x; a[7]+=f.y;
}
__device__ __forceinline__ void unp8(float* a, uint4 u){
    float2 f;
    f = __half22float2(*reinterpret_cast<__half2*>(&u.x)); a[0]=f.x; a[1]=f.y;
    f = __half22float2(*reinterpret_cast<__half2*>(&u.y)); a[2]=f.x; a[3]=f.y;
    f = __half22float2(*reinterpret_cast<__half2*>(&u.z)); a[4]=f.x; a[5]=f.y;
    f = __half22float2(*reinterpret_cast<__half2*>(&u.w)); a[6]=f.x; a[7]=f.y;
}
__device__ __forceinline__ uint4 pk8(const float* v){
    uint4 u;
    *reinterpret_cast<__half2*>(&u.x) = __floats2half2_rn(v[0], v[1]);
    *reinterpret_cast<__half2*>(&u.y) = __floats2half2_rn(v[2], v[3]);
    *reinterpret_cast<__half2*>(&u.z) = __floats2half2_rn(v[4], v[5]);
    *reinterpret_cast<__half2*>(&u.w) = __floats2half2_rn(v[6], v[7]);
    return u;
}

// fp16 K-chunk compute: 2x m16n8k16 steps over a KC=32 chunk
__device__ __forceinline__ void compute_chunk_h(
    float acc[2][8][4], const __half* As, int ldsa, const __half* Ws,
    int wm, int wn, int g, int t)
{
#pragma unroll
    for (int ks = 0; ks < 2; ks++) {
        const int kk = ks*16;
        uint32_t a[2][4], b[8][2];
#pragma unroll
        for (int mt = 0; mt < 2; mt++) {
            const __half* ap = As + (wm*32 + mt*16 + g)*ldsa + kk + 2*t;
            a[mt][0] = *reinterpret_cast<const uint32_t*>(ap);
            a[mt][1] = *reinterpret_cast<const uint32_t*>(ap + 8*ldsa);
            a[mt][2] = *reinterpret_cast<const uint32_t*>(ap + 8);
            a[mt][3] = *reinterpret_cast<const uint32_t*>(ap + 8*ldsa + 8);
        }
#pragma unroll
        for (int nt = 0; nt < 8; nt++) {
            const __half* bp = Ws + (wn*64 + nt*8 + g)*40 + kk + 2*t;
            b[nt][0] = *reinterpret_cast<const uint32_t*>(bp);
            b[nt][1] = *reinterpret_cast<const uint32_t*>(bp + 8);
        }
#pragma unroll
        for (int mt = 0; mt < 2; mt++)
#pragma unroll
            for (int nt = 0; nt < 8; nt++)
                mma16816(acc[mt][nt], a[mt], b[nt]);
    }
}

// ---------------- init ----------------
__global__ void init_k(float* __restrict__ out, const float* __restrict__ b2){
    int i = blockIdx.x*blockDim.x + threadIdx.x;
    if (i < NN) { g_deg[i] = 0; g_fill[i] = 0; out[i] = b2[0]; }
    if (i < GG*HH) g_gsum[i] = 0.f;
    if (i < GG)    g_cnt[i]  = 0.f;
}

// ---------------- CSR build ----------------
__global__ void csr_hist_k(const int* __restrict__ dst){
    int e = blockIdx.x*blockDim.x + threadIdx.x;
    if (e < EE) atomicAdd(&g_deg[dst[e]], 1);
}
__global__ __launch_bounds__(256) void csr_scan1_k(){
    __shared__ int ss[256];
    const int tid = threadIdx.x;
    const int i0  = blockIdx.x*1024 + tid*4;
    int v[4];
#pragma unroll
    for (int q = 0; q < 4; q++) v[q] = (i0+q < NN) ? g_deg[i0+q] : 0;
    int tsum = v[0]+v[1]+v[2]+v[3];
    ss[tid] = tsum; __syncthreads();
#pragma unroll
    for (int off = 1; off < 256; off <<= 1) {
        int t = (tid >= off) ? ss[tid-off] : 0;
        __syncthreads();
        ss[tid] += t;
        __syncthreads();
    }
    if (tid == 255) g_bsum[blockIdx.x] = ss[255];
    int run = ss[tid] - tsum;
#pragma unroll
    for (int q = 0; q < 4; q++) {
        if (i0+q < NN) { g_rowptr[i0+q] = run; run += v[q]; }
    }
}
__global__ __launch_bounds__(256) void csr_scan2_k(){
    __shared__ int ss[256];
    const int tid = threadIdx.x;
    int v = (tid < NB) ? g_bsum[tid] : 0;
    ss[tid] = v; __syncthreads();
#pragma unroll
    for (int off = 1; off < 256; off <<= 1) {
        int t = (tid >= off) ? ss[tid-off] : 0;
        __syncthreads();
        ss[tid] += t;
        __syncthreads();
    }
    if (tid < NB) g_boff[tid] = ss[tid] - v;   // exclusive
}
__global__ void csr_scan3_k(){
    int i = blockIdx.x*blockDim.x + threadIdx.x;
    if (i < NN) {
        g_rowptr[i] += g_boff[i >> 10];
        g_dis[i] = rsqrtf((float)g_deg[i] + 1.0f);
    }
}
__global__ void csr_fill_k(const int* __restrict__ src, const int* __restrict__ dst){
    int e = blockIdx.x*blockDim.x + threadIdx.x;
    if (e < EE) {
        int d = dst[e];
        int pos = g_rowptr[d] + atomicAdd(&g_fill[d], 1);
        g_csrc[pos] = src[e];
    }
}

// ---------------- weight prep ------------------------------------------------
__global__ void prep_w_k(const float* __restrict__ in_w, const float* __restrict__ conv_w,
                         const float* __restrict__ pw1, const float* __restrict__ hw1,
                         const float* __restrict__ pw2){
    int i = blockIdx.x*blockDim.x + threadIdx.x;
    if (i < 8192) {
        g_wr[WOFF_INW + i] = tf32r(in_w[i]);
    } else if (i < 40960) {
        int j = i - 8192;                      // hw1: 128x256
        g_wr[WOFF_HW1 + j] = tf32r(hw1[j]);
        int k = j & 255;
        if (k < 128) g_wh[HOFF_W1A + (j >> 8)*128 + k] = __float2half(hw1[j]);
    } else if (i < 57344) {
        int j = i - 40960;                     // pw2 transpose
        int r = j >> 7, c = j & 127;
        g_wr[WOFF_PW2T + c*HH + r] = tf32r(pw2[j]);
    } else if (i < 122880) {
        int j = i - 57344;                     // conv weights fp16
        g_wh[HOFF_CONV + j] = __float2half(conv_w[j]);
    } else if (i < 139264) {
        int j = i - 122880;                    // pw1 fp16
        g_wh[HOFF_PW1 + j] = __float2half(pw1[j]);
    }
}
__global__ void c2_k(const float* __restrict__ hw1, const float* __restrict__ pb2,
                     const float* __restrict__ hb1){
    int i = threadIdx.x;
    float s = 0.f;
    for (int k = 0; k < HH; k++) s = fmaf(hw1[i*256 + k], pb2[k], s);
    g_c2[i] = s + hb1[i];
}

// ---------------- TF32 GEMM (fp32 A; in-proj / Wc / gh) ----------------------
// EPI 0: out = acc (+bias) ; EPI 3: out = acc / max(g_cnt[row],1)
template<int KT, int EPI, bool OUTH, bool CVTA>
__global__ __launch_bounds__(256, 2) void mma_gemm_k(
    const float* __restrict__ A, int lda,
    const float* __restrict__ W, int ldw, const float* __restrict__ bias,
    void* __restrict__ outv, int M)
{
    constexpr int KC = 32, NC = KT / KC;
    constexpr int LDSN = 36;
    constexpr int BUFB = 128 * LDSN * 4;
    extern __shared__ char smem[];

    const int tid = threadIdx.x, wid = tid >> 5, lid = tid & 31;
    const int wm = wid & 3, wn = wid >> 2;
    const int g  = lid >> 2, t = lid & 3;
    const int brow = blockIdx.x * 128;

    float acc[2][8][4];
#pragma unroll
    for (int mt = 0; mt < 2; mt++)
#pragma unroll
        for (int nt = 0; nt < 8; nt++)
#pragma unroll
            for (int q = 0; q < 4; q++) acc[mt][nt][q] = 0.f;

#define ISSUE(ci) do {                                                          \
        char* Ad = smem + ((ci) & 1)*BUFB;                                      \
        char* Wd = smem + 2*BUFB + ((ci) & 1)*BUFB;                             \
        _Pragma("unroll")                                                       \
        for (int f = tid; f < 1024; f += 256) {                                 \
            int row = f >> 3, kq = (f & 7) * 4;                                 \
            int gr = brow + row;                                                \
            cpa16(smem_u32(Ad + (row*LDSN + kq)*4),                             \
                  A + (size_t)gr*lda + (ci)*KC + kq, (gr < M) ? 16u : 0u);      \
        }                                                                       \
        _Pragma("unroll")                                                       \
        for (int f = tid; f < 1024; f += 256) {                                 \
            int n = f >> 3, kq = (f & 7) * 4;                                   \
            cpa16(smem_u32(Wd + (n*LDSN + kq)*4),                               \
                  W + (size_t)n*ldw + (ci)*KC + kq, 16u);                       \
        }                                                                       \
        asm volatile("cp.async.commit_group;");                                 \
    } while(0)

    ISSUE(0);
#pragma unroll
    for (int ci = 0; ci < NC; ci++) {
        if (ci + 1 < NC) { ISSUE(ci + 1); asm volatile("cp.async.wait_group 1;"); }
        else             { asm volatile("cp.async.wait_group 0;"); }
        __syncthreads();
        const float* As = (const float*)(smem + (ci & 1)*BUFB);
        const float* Ws = (const float*)(smem + 2*BUFB + (ci & 1)*BUFB);
#pragma unroll
        for (int ks = 0; ks < KC/8; ks++) {
            const int kk = ks*8;
            uint32_t a[2][4], b[8][2];
#pragma unroll
            for (int mt = 0; mt < 2; mt++) {
                const float* ap = As + (wm*32 + mt*16 + g)*LDSN + kk + t;
                a[mt][0] = __float_as_uint(ap[0]);
                a[mt][1] = __float_as_uint(ap[8*LDSN]);
                a[mt][2] = __float_as_uint(ap[4]);
                a[mt][3] = __float_as_uint(ap[8*LDSN + 4]);
                if (CVTA) {
#pragma unroll
                    for (int q = 0; q < 4; q++) a[mt][q] = f2tf32(__uint_as_float(a[mt][q]));
                }
            }
#pragma unroll
            for (int nt = 0; nt < 8; nt++) {
                const float* bp = Ws + (wn*64 + nt*8 + g)*LDSN + kk + t;
                b[nt][0] = __float_as_uint(bp[0]);
                b[nt][1] = __float_as_uint(bp[4]);
            }
#pragma unroll
            for (int mt = 0; mt < 2; mt++)
#pragma unroll
                for (int nt = 0; nt < 8; nt++)
                    mma1688(acc[mt][nt], a[mt], b[nt]);
        }
        __syncthreads();
    }
#undef ISSUE

    float*  outf = (float*) outv;
    __half* outh = (__half*)outv;
#pragma unroll
    for (int mt = 0; mt < 2; mt++) {
#pragma unroll
        for (int half = 0; half < 2; half++) {
            int row = brow + wm*32 + mt*16 + g + half*8;
            if (row >= M) continue;
            size_t ro = (size_t)row*HH;
            float dsc = (EPI == 3) ? 1.f / fmaxf(g_cnt[row], 1.f) : 0.f;
#pragma unroll
            for (int nt = 0; nt < 8; nt++) {
                int col = wn*64 + nt*8 + t*2;
                float v0 = acc[mt][nt][half*2 + 0];
                float v1 = acc[mt][nt][half*2 + 1];
                if (EPI == 0) { if (bias) { v0 += bias[col]; v1 += bias[col+1]; } }
                else if (EPI == 3) { v0 *= dsc; v1 *= dsc; }
                if (OUTH) *reinterpret_cast<__half2*>(outh + ro + col) = __floats2half2_rn(v0, v1);
                else      *reinterpret_cast<float2*>(outf + ro + col) = make_float2(v0, v1);
            }
        }
    }
}

// ---------------- fp16 conv GEMM: hwsc = half((h @ Wl^T) * dis[row]) ---------
__global__ __launch_bounds__(256, 2) void conv_gemm_k(
    const __half* __restrict__ A, const __half* __restrict__ W,
    __half* __restrict__ out, int M)
{
    constexpr int NC = 4, LDS = 40;
    constexpr int TB = 128 * LDS * 2;   // 10240 bytes per tile
    extern __shared__ char smem[];

    const int tid = threadIdx.x, wid = tid >> 5, lid = tid & 31;
    const int wm = wid & 3, wn = wid >> 2;
    const int g  = lid >> 2, t = lid & 3;
    const int brow = blockIdx.x * 128;

    float acc[2][8][4];
#pragma unroll
    for (int mt = 0; mt < 2; mt++)
#pragma unroll
        for (int nt = 0; nt < 8; nt++)
#pragma unroll
            for (int q = 0; q < 4; q++) acc[mt][nt][q] = 0.f;

#define CISSUE(ci) do {                                                         \
        char* Ad = smem + ((ci) & 1)*TB;                                        \
        char* Wd = smem + 2*TB + ((ci) & 1)*TB;                                 \
        _Pragma("unroll")                                                       \
        for (int f = tid; f < 512; f += 256) {                                  \
            int row = f >> 2, kq = (f & 3) * 8;                                 \
            int gr = brow + row;                                                \
            cpa16(smem_u32(Ad + (row*LDS + kq)*2),                              \
                  A + (size_t)gr*HH + (ci)*32 + kq, (gr < M) ? 16u : 0u);       \
        }                                                                       \
        _Pragma("unroll")                                                       \
        for (int f = tid; f < 512; f += 256) {                                  \
            int n = f >> 2, kq = (f & 3) * 8;                                   \
            cpa16(smem_u32(Wd + (n*LDS + kq)*2),                                \
                  W + (size_t)n*HH + (ci)*32 + kq, 16u);                        \
        }                                                                       \
        asm volatile("cp.async.commit_group;");                                 \
    } while(0)

    CISSUE(0);
#pragma unroll
    for (int ci = 0; ci < NC; ci++) {
        if (ci + 1 < NC) { CISSUE(ci + 1); asm volatile("cp.async.wait_group 1;"); }
        else             { asm volatile("cp.async.wait_group 0;"); }
        __syncthreads();
        compute_chunk_h(acc, (const __half*)(smem + (ci & 1)*TB), LDS,
                        (const __half*)(smem + 2*TB + (ci & 1)*TB), wm, wn, g, t);
        __syncthreads();
    }
#undef CISSUE

#pragma unroll
    for (int mt = 0; mt < 2; mt++) {
#pragma unroll
        for (int half = 0; half < 2; half++) {
            int row = brow + wm*32 + mt*16 + g + half*8;
            if (row >= M) continue;
            size_t ro = (size_t)row*HH;
            float dsc = g_dis[row];
#pragma unroll
            for (int nt = 0; nt < 8; nt++) {
                int col = wn*64 + nt*8 + t*2;
                *reinterpret_cast<__half2*>(out + ro + col) =
                    __floats2half2_rn(acc[mt][nt][half*2+0]*dsc, acc[mt][nt][half*2+1]*dsc);
            }
        }
    }
}

// ---------------- fused head GEMM (all fp16 operands) ------------------------
// phase 1: t1 = silu(h @ pw1^T + pb1) -> smem (fp16)
// phase 2: acc = h @ W1a^T + t1 @ Wc^T ; hid = silu(acc + c2 + gh[batch]) ;
//          out[row] += hid . w2
__global__ __launch_bounds__(256, 2) void head_gemm_k(
    const float* __restrict__ w2, const int* __restrict__ batch,
    const float* __restrict__ pb1, float* __restrict__ out)
{
    constexpr int LDS = 40, T1LD = 136;
    constexpr int TB = 128 * LDS * 2;           // 10240
    extern __shared__ char smem[];
    __half* t1s = (__half*)(smem + 4*TB);       // 128*136*2 = 34816

    const int tid = threadIdx.x, wid = tid >> 5, lid = tid & 31;
    const int wm = wid & 3, wn = wid >> 2;
    const int g  = lid >> 2, t = lid & 3;
    const int brow = blockIdx.x * 128;

    float acc[2][8][4];
#pragma unroll
    for (int mt = 0; mt < 2; mt++)
#pragma unroll
        for (int nt = 0; nt < 8; nt++)
#pragma unroll
            for (int q = 0; q < 4; q++) acc[mt][nt][q] = 0.f;

#define HA_LOAD(ci) do {                                                        \
        char* Ad = smem + ((ci) & 1)*TB;                                        \
        _Pragma("unroll")                                                       \
        for (int f = tid; f < 512; f += 256) {                                  \
            int row = f >> 2, kq = (f & 3) * 8;                                 \
            int gr = brow + row;                                                \
            cpa16(smem_u32(Ad + (row*LDS + kq)*2),                              \
                  g_h + (size_t)gr*HH + (((ci)*32) & 127) + kq,                 \
                  (gr < NN) ? 16u : 0u);                                        \
        } } while(0)
#define HW_LOAD(ci, WP, KOFF) do {                                              \
        char* Wd = smem + 2*TB + ((ci) & 1)*TB;                                 \
        _Pragma("unroll")                                                       \
        for (int f = tid; f < 512; f += 256) {                                  \
            int n = f >> 2, kq = (f & 3) * 8;                                   \
            cpa16(smem_u32(Wd + (n*LDS + kq)*2),                                \
                  (WP) + (size_t)n*HH + (KOFF) + kq, 16u);                      \
        } } while(0)

    // ---- phase 1: acc = h @ pw1^T ----
    const __half* PW1 = g_wh + HOFF_PW1;
    HA_LOAD(0); HW_LOAD(0, PW1, 0);
    asm volatile("cp.async.commit_group;");
#pragma unroll
    for (int ci = 0; ci < 4; ci++) {
        if (ci + 1 < 4) {
            HA_LOAD(ci+1); HW_LOAD(ci+1, PW1, (ci+1)*32);
            asm volatile("cp.async.commit_group;");
            asm volatile("cp.async.wait_group 1;");
        } else asm volatile("cp.async.wait_group 0;");
        __syncthreads();
        compute_chunk_h(acc, (const __half*)(smem + (ci & 1)*TB), LDS,
                        (const __half*)(smem + 2*TB + (ci & 1)*TB), wm, wn, g, t);
        __syncthreads();
    }

    // phase-1 epilogue -> t1s (fp16), then reset acc
#pragma unroll
    for (int mt = 0; mt < 2; mt++)
#pragma unroll
        for (int half = 0; half < 2; half++) {
            int m = wm*32 + mt*16 + g + half*8;
#pragma unroll
            for (int nt = 0; nt < 8; nt++) {
                int col = wn*64 + nt*8 + t*2;
                float v0 = siluf(acc[mt][nt][half*2+0] + pb1[col]);
                float v1 = siluf(acc[mt][nt][half*2+1] + pb1[col+1]);
                *reinterpret_cast<__half2*>(t1s + m*T1LD + col) = __floats2half2_rn(v0, v1);
            }
        }
#pragma unroll
    for (int mt = 0; mt < 2; mt++)
#pragma unroll
        for (int nt = 0; nt < 8; nt++)
#pragma unroll
            for (int q = 0; q < 4; q++) acc[mt][nt][q] = 0.f;
    __syncthreads();

    // ---- phase 2: acc = h @ W1a^T + t1 @ Wc^T (K=256) ----
    const __half* W1A = g_wh + HOFF_W1A;
    HA_LOAD(0); HW_LOAD(0, W1A, 0);
    asm volatile("cp.async.commit_group;");
#pragma unroll
    for (int ci = 0; ci < 8; ci++) {
        if (ci + 1 < 8) {
            if (ci + 1 < 4) { HA_LOAD(ci+1); HW_LOAD(ci+1, W1A, (ci+1)*32); }
            else            { HW_LOAD(ci+1, g_wch, ((ci+1)-4)*32); }
            asm volatile("cp.async.commit_group;");
            asm volatile("cp.async.wait_group 1;");
        } else asm volatile("cp.async.wait_group 0;");
        __syncthreads();
        if (ci < 4)
            compute_chunk_h(acc, (const __half*)(smem + (ci & 1)*TB), LDS,
                            (const __half*)(smem + 2*TB + (ci & 1)*TB), wm, wn, g, t);
        else
            compute_chunk_h(acc, t1s + (ci - 4)*32, T1LD,
                            (const __half*)(smem + 2*TB + (ci & 1)*TB), wm, wn, g, t);
        __syncthreads();
    }
#undef HA_LOAD
#undef HW_LOAD

    // ---- final epilogue: silu + dot(w2) + red.add ----
#pragma unroll
    for (int mt = 0; mt < 2; mt++) {
#pragma unroll
        for (int half = 0; half < 2; half++) {
            int row = brow + wm*32 + mt*16 + g + half*8;
            float partial = 0.f;
            if (row < NN) {
                const float* ghrow = g_gh + (size_t)batch[row]*HH;
#pragma unroll
                for (int nt = 0; nt < 8; nt++) {
                    int col = wn*64 + nt*8 + t*2;
                    float v0 = siluf(acc[mt][nt][half*2+0] + g_c2[col]   + ghrow[col]);
                    float v1 = siluf(acc[mt][nt][half*2+1] + g_c2[col+1] + ghrow[col+1]);
                    partial = fmaf(v0, w2[col], partial);
                    partial = fmaf(v1, w2[col+1], partial);
                }
            }
            partial += __shfl_xor_sync(0xffffffffu, partial, 1);
            partial += __shfl_xor_sync(0xffffffffu, partial, 2);
            if (t == 0 && row < NN)
                asm volatile("red.global.add.f32 [%0], %1;" :: "l"(out + row), "f"(partial) : "memory");
        }
    }
}

// ---- fused neighbor-gather + silu + LN + residual (+pool) ------------------
template<bool POOL>
__global__ __launch_bounds__(256) void gather_ln_k(const float* __restrict__ bias,
                                                   const float* __restrict__ lng,
                                                   const float* __restrict__ lnb,
                                                   const int* __restrict__ batch)
{
    int node = blockIdx.x * 16 + (threadIdx.x >> 4);
    if (node >= NN) return;
    const int l16 = threadIdx.x & 15;
    const int c0  = l16 * 8;
    const int cnt   = g_deg[node];
    const int start = g_rowptr[node];
    const float di  = g_dis[node];
    const size_t off = (size_t)node*HH + c0;

    float a[8] = {0,0,0,0,0,0,0,0};
    acc8(a, *reinterpret_cast<const uint4*>(g_hw + off));   // self term (already *di)

    for (int base = 0; base < cnt; base += 4) {
        int m = cnt - base;
        int i0 = g_csrc[start + base];
        int i1 = (m > 1) ? g_csrc[start + base + 1] : i0;
        int i2 = (m > 2) ? g_csrc[start + base + 2] : i0;
        int i3 = (m > 3) ? g_csrc[start + base + 3] : i0;
        uint4 u0 = *reinterpret_cast<const uint4*>(g_hw + (size_t)i0*HH + c0);
        uint4 u1 = *reinterpret_cast<const uint4*>(g_hw + (size_t)i1*HH + c0);
        uint4 u2 = *reinterpret_cast<const uint4*>(g_hw + (size_t)i2*HH + c0);
        uint4 u3 = *reinterpret_cast<const uint4*>(g_hw + (size_t)i3*HH + c0);
        acc8(a, u0);
        if (m > 1) acc8(a, u1);
        if (m > 2) acc8(a, u2);
        if (m > 3) acc8(a, u3);
    }

    float4 b0 = ld4(bias + c0), b1 = ld4(bias + c0 + 4);
    float s[8];
    s[0] = siluf(fmaf(a[0], di, b0.x)); s[1] = siluf(fmaf(a[1], di, b0.y));
    s[2] = siluf(fmaf(a[2], di, b0.z)); s[3] = siluf(fmaf(a[3], di, b0.w));
    s[4] = siluf(fmaf(a[4], di, b1.x)); s[5] = siluf(fmaf(a[5], di, b1.y));
    s[6] = siluf(fmaf(a[6], di, b1.z)); s[7] = siluf(fmaf(a[7], di, b1.w));

    float sum = 0.f, sq = 0.f;
#pragma unroll
    for (int q = 0; q < 8; q++) { sum += s[q]; sq = fmaf(s[q], s[q], sq); }
#pragma unroll
    for (int o = 1; o < 16; o <<= 1) {
        sum += __shfl_xor_sync(0xffffffffu, sum, o);
        sq  += __shfl_xor_sync(0xffffffffu, sq,  o);
    }
    float mu  = sum * (1.f/128.f);
    float var = sq * (1.f/128.f) - mu*mu;
    float inv = rsqrtf(var + 1e-5f);

    float4 g0 = ld4(lng + c0), g1 = ld4(lng + c0 + 4);
    float4 e0 = ld4(lnb + c0), e1 = ld4(lnb + c0 + 4);
    float hv[8];
    unp8(hv, *reinterpret_cast<const uint4*>(g_h + off));
    hv[0] += (s[0]-mu)*inv*g0.x + e0.x;
    hv[1] += (s[1]-mu)*inv*g0.y + e0.y;
    hv[2] += (s[2]-mu)*inv*g0.z + e0.z;
    hv[3] += (s[3]-mu)*inv*g0.w + e0.w;
    hv[4] += (s[4]-mu)*inv*g1.x + e1.x;
    hv[5] += (s[5]-mu)*inv*g1.y + e1.y;
    hv[6] += (s[6]-mu)*inv*g1.z + e1.z;
    hv[7] += (s[7]-mu)*inv*g1.w + e1.w;
    *reinterpret_cast<uint4*>(g_h + off) = pk8(hv);

    if (POOL) {
        int b = batch[node];
        float* p = g_gsum + (size_t)b*HH + c0;
        asm volatile("red.global.add.v4.f32 [%0], {%1,%2,%3,%4};"
                     :: "l"(p), "f"(hv[0]), "f"(hv[1]), "f"(hv[2]), "f"(hv[3]) : "memory");
        asm volatile("red.global.add.v4.f32 [%0], {%1,%2,%3,%4};"
                     :: "l"(p+4), "f"(hv[4]), "f"(hv[5]), "f"(hv[6]), "f"(hv[7]) : "memory");
        if (l16 == 0) atomicAdd(&g_cnt[b], 1.0f);
    }
}

// ---------------- launch ----------------
extern "C" void kernel_launch(void* const* d_in, const int* in_sizes, int n_in,
                              void* d_out, int out_size)
{
    const float* x      = (const float*)d_in[0];
    const int*   ei     = (const int*)  d_in[1];
    const int*   src    = ei;
    const int*   dst    = ei + EE;
    const int*   batch  = (const int*)  d_in[2];
    const float* in_w   = (const float*)d_in[3];
    const float* in_b   = (const float*)d_in[4];
    const float* conv_w = (const float*)d_in[5];
    const float* conv_b = (const float*)d_in[6];
    const float* ln_g   = (const float*)d_in[7];
    const float* ln_b   = (const float*)d_in[8];
    const float* pw1    = (const float*)d_in[9];
    const float* pb1    = (const float*)d_in[10];
    const float* pw2    = (const float*)d_in[11];
    const float* pb2    = (const float*)d_in[12];
    const float* hw1    = (const float*)d_in[13];
    const float* hb1    = (const float*)d_in[14];
    const float* hw2    = (const float*)d_in[15];
    const float* hb2    = (const float*)d_in[16];
    float* out = (float*)d_out;

    float *p_gsum, *p_gh, *p_wr;
    __half *p_h, *p_hw, *p_wh, *p_wch;
    cudaGetSymbolAddress((void**)&p_h,    g_h);
    cudaGetSymbolAddress((void**)&p_hw,   g_hw);
    cudaGetSymbolAddress((void**)&p_gsum, g_gsum);
    cudaGetSymbolAddress((void**)&p_gh,   g_gh);
    cudaGetSymbolAddress((void**)&p_wr,   g_wr);
    cudaGetSymbolAddress((void**)&p_wh,   g_wh);
    cudaGetSymbolAddress((void**)&p_wch,  g_wch);

    static cudaStream_t s_csr = nullptr, s_wp = nullptr;
    static cudaEvent_t  ev_fork = nullptr, ev_csr = nullptr, ev_wp = nullptr;
    if (s_csr == nullptr) {
        cudaStreamCreateWithFlags(&s_csr, cudaStreamNonBlocking);
        cudaStreamCreateWithFlags(&s_wp,  cudaStreamNonBlocking);
        cudaEventCreateWithFlags(&ev_fork, cudaEventDisableTiming);
        cudaEventCreateWithFlags(&ev_csr,  cudaEventDisableTiming);
        cudaEventCreateWithFlags(&ev_wp,   cudaEventDisableTiming);
    }

    const int TPB = 256;
    const int gI  = (GG*HH + TPB - 1) / TPB;     // covers NN too
    const int gN  = (NN + TPB - 1) / TPB;
    const int gE  = (EE + TPB - 1) / TPB;
    const int gG16 = (NN + 15) / 16;
    const int gGm = (NN + 127) / 128;
    const int gGg = GG / 128;
    const int gW  = (139264 + TPB - 1) / TPB;

    const int SMB_F    = 4 * 128 * 36 * 4;   // 73728 (tf32 GEMM)
    const int SMB_CONV = 4 * 128 * 40 * 2;   // 40960 (fp16 GEMM)
    const int SMB_HEAD = SMB_CONV + 128*136*2;  // 75776
    cudaFuncSetAttribute(mma_gemm_k< 64,0,true ,true >, cudaFuncAttributeMaxDynamicSharedMemorySize, SMB_F);
    cudaFuncSetAttribute(mma_gemm_k<128,0,true ,false>, cudaFuncAttributeMaxDynamicSharedMemorySize, SMB_F);
    cudaFuncSetAttribute(mma_gemm_k<128,3,false,true >, cudaFuncAttributeMaxDynamicSharedMemorySize, SMB_F);
    cudaFuncSetAttribute(conv_gemm_k, cudaFuncAttributeMaxDynamicSharedMemorySize, SMB_CONV);
    cudaFuncSetAttribute(head_gemm_k, cudaFuncAttributeMaxDynamicSharedMemorySize, SMB_HEAD);

    // ---- init, then fork: CSR chain || weight-prep + in-proj ----
    init_k<<<gI, TPB>>>(out, hb2);
    cudaEventRecord(ev_fork, 0);
    cudaStreamWaitEvent(s_csr, ev_fork, 0);
    cudaStreamWaitEvent(s_wp,  ev_fork, 0);

    csr_hist_k <<<gE, TPB, 0, s_csr>>>(dst);
    csr_scan1_k<<<NB, TPB, 0, s_csr>>>();
    csr_scan2_k<<<1,  TPB, 0, s_csr>>>();
    csr_scan3_k<<<gN, TPB, 0, s_csr>>>();
    csr_fill_k <<<gE, TPB, 0, s_csr>>>(src, dst);
    cudaEventRecord(ev_csr, s_csr);

    prep_w_k<<<gW, TPB, 0, s_wp>>>(in_w, conv_w, pw1, hw1, pw2);
    c2_k<<<1, 128, 0, s_wp>>>(hw1, pb2, hb1);
    // Wc = W1a_h @ pw2 -> fp16
    mma_gemm_k<128,0,true,false><<<1, TPB, SMB_F, s_wp>>>(
        p_wr + WOFF_HW1, 256, p_wr + WOFF_PW2T, 128, nullptr, p_wch, 128);
    // in-proj: h = x @ in_w^T + in_b -> fp16
    mma_gemm_k<64,0,true,true><<<gGm, TPB, SMB_F, s_wp>>>(
        x, 64, p_wr + WOFF_INW, 64, in_b, p_h, NN);
    cudaEventRecord(ev_wp, s_wp);

    cudaStreamWaitEvent(0, ev_csr, 0);
    cudaStreamWaitEvent(0, ev_wp, 0);

    // ---- GCN layers (fp16 MMA conv + fused gather) ----
    for (int l = 0; l < 4; l++) {
        conv_gemm_k<<<gGm, TPB, SMB_CONV>>>(p_h, p_wh + HOFF_CONV + (size_t)l*HH*HH, p_hw, NN);
        if (l < 3) gather_ln_k<false><<<gG16, TPB>>>(conv_b + l*HH, ln_g + l*HH, ln_b + l*HH, batch);
        else       gather_ln_k<true ><<<gG16, TPB>>>(conv_b + l*HH, ln_g + l*HH, ln_b + l*HH, batch);
    }

    // gh = (gsum/cnt) @ W1b^T
    mma_gemm_k<128,3,false,true><<<gGg, TPB, SMB_F>>>(
        p_gsum, 128, p_wr + WOFF_HW1 + 128, 256, nullptr, p_gh, GG);

    // fused head (fp16 phases)
    head_gemm_k<<<gGm, TPB, SMB_HEAD>>>(hw2, batch, pb1, out);
}

// round 15
// speedup vs baseline: 1.1728x; 1.0449x over previous
#include <cuda_runtime.h>
#include <cuda_fp16.h>
#include <cstdint>

#define NN 200000
#define EE 600000
#define GG 8192
#define HH 128
#define NB 196            // scan blocks: 196*1024 >= NN

// fp32 (tf32-rounded) weight scratch offsets (floats)
#define WOFF_INW  0
#define WOFF_HW1  8192
#define WOFF_PW2T 40960
#define WTOT      57344
// fp16 weight scratch offsets (halves)
#define HOFF_CONV 0
#define HOFF_PW1  65536
#define HOFF_W1A  81920
#define HTOT      98304

#define WAITG(n) asm volatile("cp.async.wait_group %0;" :: "n"(n))
#define COMMITG() asm volatile("cp.async.commit_group;")

// ---------------- scratch (device globals: allocation-free) ----------------
__device__ __half g_h  [(size_t)NN*HH];     // residual stream (fp16)
__device__ __half g_hw [(size_t)NN*HH];     // conv outputs pre-scaled by dis (fp16)
__device__ float  g_dis[NN];
__device__ float  g_gsum[(size_t)GG*HH];
__device__ float  g_cnt[GG];
__device__ float  g_gh [(size_t)GG*HH];
__device__ __half g_wch[HH*HH];             // Wc (fp16)
__device__ float  g_c2  [HH];
__device__ float  g_wr  [WTOT];             // tf32-rounded fp32 weights
__device__ __half g_wh  [HTOT];             // fp16 weights (conv, pw1, w1a)
// CSR
__device__ int g_deg[NN];
__device__ int g_fill[NN];
__device__ int g_rowptr[NN];
__device__ int g_csrc[EE];
__device__ int g_bsum[256];
__device__ int g_boff[256];

// ---------------- small helpers ----------------
__device__ __forceinline__ float4 ld4(const float* p){ return *reinterpret_cast<const float4*>(p); }
__device__ __forceinline__ float siluf(float x){ return x / (1.f + __expf(-x)); }
__device__ __forceinline__ uint32_t f2tf32(float f){
    uint32_t u;
    asm("cvt.rna.tf32.f32 %0, %1;" : "=r"(u) : "f"(f));
    return u;
}
__device__ __forceinline__ float tf32r(float f){ return __uint_as_float(f2tf32(f)); }
__device__ __forceinline__ uint32_t smem_u32(const void* p){
    uint32_t a;
    asm("{ .reg .u64 t; cvta.to.shared.u64 t, %1; cvt.u32.u64 %0, t; }" : "=r"(a) : "l"(p));
    return a;
}
__device__ __forceinline__ void cpa16(uint32_t sa, const void* gp, uint32_t sz){
    asm volatile("cp.async.cg.shared.global [%0], [%1], 16, %2;" :: "r"(sa), "l"(gp), "r"(sz));
}
__device__ __forceinline__ void mma1688(float* d, const uint32_t* a, const uint32_t* b){
    asm volatile("mma.sync.aligned.m16n8k8.row.col.f32.tf32.tf32.f32 "
        "{%0,%1,%2,%3}, {%4,%5,%6,%7}, {%8,%9}, {%0,%1,%2,%3};"
        : "+f"(d[0]), "+f"(d[1]), "+f"(d[2]), "+f"(d[3])
        : "r"(a[0]), "r"(a[1]), "r"(a[2]), "r"(a[3]), "r"(b[0]), "r"(b[1]));
}
__device__ __forceinline__ void mma16816(float* d, const uint32_t* a, const uint32_t* b){
    asm volatile("mma.sync.aligned.m16n8k16.row.col.f32.f16.f16.f32 "
        "{%0,%1,%2,%3}, {%4,%5,%6,%7}, {%8,%9}, {%0,%1,%2,%3};"
        : "+f"(d[0]), "+f"(d[1]), "+f"(d[2]), "+f"(d[3])
        : "r"(a[0]), "r"(a[1]), "r"(a[2]), "r"(a[3]), "r"(b[0]), "r"(b[1]));
}
__device__ __forceinline__ void acc8(float* a, uint4 u){
    float2 f;
    f = __half22float2(*reinterpret_cast<__half2*>(&u.x)); a[0]+=f.x; a[1]+=f.y;
    f = __half22float2(*reinterpret_cast<__half2*>(&u.y)); a[2]+=f.x; a[3]+=f.y;
    f = __half22float2(*reinterpret_cast<__half2*>(&u.z)); a[4]+=f.x; a[5]+=f.y;
    f = __half22float2(*reinterpret_cast<__half2*>(&u.w)); a[6]+=f.x; a[7]+=f.y;
}
__device__ __forceinline__ void unp8(float* a, uint4 u){
    float2 f;
    f = __half22float2(*reinterpret_cast<__half2*>(&u.x)); a[0]=f.x; a[1]=f.y;
    f = __half22float2(*reinterpret_cast<__half2*>(&u.y)); a[2]=f.x; a[3]=f.y;
    f = __half22float2(*reinterpret_cast<__half2*>(&u.z)); a[4]=f.x; a[5]=f.y;
    f = __half22float2(*reinterpret_cast<__half2*>(&u.w)); a[6]=f.x; a[7]=f.y;
}
__device__ __forceinline__ uint4 pk8(const float* v){
    uint4 u;
    *reinterpret_cast<__half2*>(&u.x) = __floats2half2_rn(v[0], v[1]);
    *reinterpret_cast<__half2*>(&u.y) = __floats2half2_rn(v[2], v[3]);
    *reinterpret_cast<__half2*>(&u.z) = __floats2half2_rn(v[4], v[5]);
    *reinterpret_cast<__half2*>(&u.w) = __floats2half2_rn(v[6], v[7]);
    return u;
}

// fp16 K-chunk compute: 2x m16n8k16 steps over a KC=32 chunk
__device__ __forceinline__ void compute_chunk_h(
    float acc[2][8][4], const __half* As, int ldsa, const __half* Ws,
    int wm, int wn, int g, int t)
{
#pragma unroll
    for (int ks = 0; ks < 2; ks++) {
        const int kk = ks*16;
        uint32_t a[2][4], b[8][2];
#pragma unroll
        for (int mt = 0; mt < 2; mt++) {
            const __half* ap = As + (wm*32 + mt*16 + g)*ldsa + kk + 2*t;
            a[mt][0] = *reinterpret_cast<const uint32_t*>(ap);
            a[mt][1] = *reinterpret_cast<const uint32_t*>(ap + 8*ldsa);
            a[mt][2] = *reinterpret_cast<const uint32_t*>(ap + 8);
            a[mt][3] = *reinterpret_cast<const uint32_t*>(ap + 8*ldsa + 8);
        }
#pragma unroll
        for (int nt = 0; nt < 8; nt++) {
            const __half* bp = Ws + (wn*64 + nt*8 + g)*40 + kk + 2*t;
            b[nt][0] = *reinterpret_cast<const uint32_t*>(bp);
            b[nt][1] = *reinterpret_cast<const uint32_t*>(bp + 8);
        }
#pragma unroll
        for (int mt = 0; mt < 2; mt++)
#pragma unroll
            for (int nt = 0; nt < 8; nt++)
                mma16816(acc[mt][nt], a[mt], b[nt]);
    }
}

// ---------------- init ----------------
__global__ void init_k(float* __restrict__ out, const float* __restrict__ b2){
    int i = blockIdx.x*blockDim.x + threadIdx.x;
    if (i < NN) { g_deg[i] = 0; g_fill[i] = 0; out[i] = b2[0]; }
    if (i < GG*HH) g_gsum[i] = 0.f;
    if (i < GG)    g_cnt[i]  = 0.f;
}

// ---------------- CSR build ----------------
__global__ void csr_hist_k(const int* __restrict__ dst){
    int e = blockIdx.x*blockDim.x + threadIdx.x;
    if (e < EE) atomicAdd(&g_deg[dst[e]], 1);
}
__global__ __launch_bounds__(256) void csr_scan1_k(){
    __shared__ int ss[256];
    const int tid = threadIdx.x;
    const int i0  = blockIdx.x*1024 + tid*4;
    int v[4];
#pragma unroll
    for (int q = 0; q < 4; q++) v[q] = (i0+q < NN) ? g_deg[i0+q] : 0;
    int tsum = v[0]+v[1]+v[2]+v[3];
    ss[tid] = tsum; __syncthreads();
#pragma unroll
    for (int off = 1; off < 256; off <<= 1) {
        int t = (tid >= off) ? ss[tid-off] : 0;
        __syncthreads();
        ss[tid] += t;
        __syncthreads();
    }
    if (tid == 255) g_bsum[blockIdx.x] = ss[255];
    int run = ss[tid] - tsum;
#pragma unroll
    for (int q = 0; q < 4; q++) {
        if (i0+q < NN) { g_rowptr[i0+q] = run; run += v[q]; }
    }
}
__global__ __launch_bounds__(256) void csr_scan2_k(){
    __shared__ int ss[256];
    const int tid = threadIdx.x;
    int v = (tid < NB) ? g_bsum[tid] : 0;
    ss[tid] = v; __syncthreads();
#pragma unroll
    for (int off = 1; off < 256; off <<= 1) {
        int t = (tid >= off) ? ss[tid-off] : 0;
        __syncthreads();
        ss[tid] += t;
        __syncthreads();
    }
    if (tid < NB) g_boff[tid] = ss[tid] - v;   // exclusive
}
__global__ void csr_scan3_k(){
    int i = blockIdx.x*blockDim.x + threadIdx.x;
    if (i < NN) {
        g_rowptr[i] += g_boff[i >> 10];
        g_dis[i] = rsqrtf((float)g_deg[i] + 1.0f);
    }
}
__global__ void csr_fill_k(const int* __restrict__ src, const int* __restrict__ dst){
    int e = blockIdx.x*blockDim.x + threadIdx.x;
    if (e < EE) {
        int d = dst[e];
        int pos = g_rowptr[d] + atomicAdd(&g_fill[d], 1);
        g_csrc[pos] = src[e];
    }
}

// ---------------- weight prep ------------------------------------------------
__global__ void prep_w_k(const float* __restrict__ in_w, const float* __restrict__ conv_w,
                         const float* __restrict__ pw1, const float* __restrict__ hw1,
                         const float* __restrict__ pw2){
    int i = blockIdx.x*blockDim.x + threadIdx.x;
    if (i < 8192) {
        g_wr[WOFF_INW + i] = tf32r(in_w[i]);
    } else if (i < 40960) {
        int j = i - 8192;                      // hw1: 128x256
        g_wr[WOFF_HW1 + j] = tf32r(hw1[j]);
        int k = j & 255;
        if (k < 128) g_wh[HOFF_W1A + (j >> 8)*128 + k] = __float2half(hw1[j]);
    } else if (i < 57344) {
        int j = i - 40960;                     // pw2 transpose
        int r = j >> 7, c = j & 127;
        g_wr[WOFF_PW2T + c*HH + r] = tf32r(pw2[j]);
    } else if (i < 122880) {
        int j = i - 57344;                     // conv weights fp16
        g_wh[HOFF_CONV + j] = __float2half(conv_w[j]);
    } else if (i < 139264) {
        int j = i - 122880;                    // pw1 fp16
        g_wh[HOFF_PW1 + j] = __float2half(pw1[j]);
    }
}
__global__ void c2_k(const float* __restrict__ hw1, const float* __restrict__ pb2,
                     const float* __restrict__ hb1){
    int i = threadIdx.x;
    float s = 0.f;
    for (int k = 0; k < HH; k++) s = fmaf(hw1[i*256 + k], pb2[k], s);
    g_c2[i] = s + hb1[i];
}

// ---------------- TF32 GEMM (fp32 A; in-proj / Wc / gh) ----------------------
// EPI 0: out = acc (+bias) ; EPI 3: out = acc / max(g_cnt[row],1)
template<int KT, int EPI, bool OUTH, bool CVTA>
__global__ __launch_bounds__(256, 2) void mma_gemm_k(
    const float* __restrict__ A, int lda,
    const float* __restrict__ W, int ldw, const float* __restrict__ bias,
    void* __restrict__ outv, int M)
{
    constexpr int KC = 32, NC = KT / KC;
    constexpr int LDSN = 36;
    constexpr int BUFB = 128 * LDSN * 4;
    extern __shared__ char smem[];

    const int tid = threadIdx.x, wid = tid >> 5, lid = tid & 31;
    const int wm = wid & 3, wn = wid >> 2;
    const int g  = lid >> 2, t = lid & 3;
    const int brow = blockIdx.x * 128;

    float acc[2][8][4];
#pragma unroll
    for (int mt = 0; mt < 2; mt++)
#pragma unroll
        for (int nt = 0; nt < 8; nt++)
#pragma unroll
            for (int q = 0; q < 4; q++) acc[mt][nt][q] = 0.f;

#define ISSUE(ci) do {                                                          \
        char* Ad = smem + ((ci) & 1)*BUFB;                                      \
        char* Wd = smem + 2*BUFB + ((ci) & 1)*BUFB;                             \
        _Pragma("unroll")                                                       \
        for (int f = tid; f < 1024; f += 256) {                                 \
            int row = f >> 3, kq = (f & 7) * 4;                                 \
            int gr = brow + row;                                                \
            cpa16(smem_u32(Ad + (row*LDSN + kq)*4),                             \
                  A + (size_t)gr*lda + (ci)*KC + kq, (gr < M) ? 16u : 0u);      \
        }                                                                       \
        _Pragma("unroll")                                                       \
        for (int f = tid; f < 1024; f += 256) {                                 \
            int n = f >> 3, kq = (f & 7) * 4;                                   \
            cpa16(smem_u32(Wd + (n*LDSN + kq)*4),                               \
                  W + (size_t)n*ldw + (ci)*KC + kq, 16u);                       \
        }                                                                       \
        COMMITG();                                                              \
    } while(0)

    ISSUE(0);
#pragma unroll
    for (int ci = 0; ci < NC; ci++) {
        if (ci + 1 < NC) { ISSUE(ci + 1); WAITG(1); }
        else             { WAITG(0); }
        __syncthreads();
        const float* As = (const float*)(smem + (ci & 1)*BUFB);
        const float* Ws = (const float*)(smem + 2*BUFB + (ci & 1)*BUFB);
#pragma unroll
        for (int ks = 0; ks < KC/8; ks++) {
            const int kk = ks*8;
            uint32_t a[2][4], b[8][2];
#pragma unroll
            for (int mt = 0; mt < 2; mt++) {
                const float* ap = As + (wm*32 + mt*16 + g)*LDSN + kk + t;
                a[mt][0] = __float_as_uint(ap[0]);
                a[mt][1] = __float_as_uint(ap[8*LDSN]);
                a[mt][2] = __float_as_uint(ap[4]);
                a[mt][3] = __float_as_uint(ap[8*LDSN + 4]);
                if (CVTA) {
#pragma unroll
                    for (int q = 0; q < 4; q++) a[mt][q] = f2tf32(__uint_as_float(a[mt][q]));
                }
            }
#pragma unroll
            for (int nt = 0; nt < 8; nt++) {
                const float* bp = Ws + (wn*64 + nt*8 + g)*LDSN + kk + t;
                b[nt][0] = __float_as_uint(bp[0]);
                b[nt][1] = __float_as_uint(bp[4]);
            }
#pragma unroll
            for (int mt = 0; mt < 2; mt++)
#pragma unroll
                for (int nt = 0; nt < 8; nt++)
                    mma1688(acc[mt][nt], a[mt], b[nt]);
        }
        __syncthreads();
    }
#undef ISSUE

    float*  outf = (float*) outv;
    __half* outh = (__half*)outv;
#pragma unroll
    for (int mt = 0; mt < 2; mt++) {
#pragma unroll
        for (int half = 0; half < 2; half++) {
            int row = brow + wm*32 + mt*16 + g + half*8;
            if (row >= M) continue;
            size_t ro = (size_t)row*HH;
            float dsc = (EPI == 3) ? 1.f / fmaxf(g_cnt[row], 1.f) : 0.f;
#pragma unroll
            for (int nt = 0; nt < 8; nt++) {
                int col = wn*64 + nt*8 + t*2;
                float v0 = acc[mt][nt][half*2 + 0];
                float v1 = acc[mt][nt][half*2 + 1];
                if (EPI == 0) { if (bias) { v0 += bias[col]; v1 += bias[col+1]; } }
                else if (EPI == 3) { v0 *= dsc; v1 *= dsc; }
                if (OUTH) *reinterpret_cast<__half2*>(outh + ro + col) = __floats2half2_rn(v0, v1);
                else      *reinterpret_cast<float2*>(outf + ro + col) = make_float2(v0, v1);
            }
        }
    }
}

// ---------------- fp16 conv GEMM: hwsc = half((h @ Wl^T) * dis[row]) ---------
// Full prefetch: all 4 A chunks + 4 W chunks issued at t=0 (8 x 10240 B smem).
__global__ __launch_bounds__(256, 2) void conv_gemm_k(
    const __half* __restrict__ A, const __half* __restrict__ W,
    __half* __restrict__ out, int M)
{
    constexpr int LDS = 40;
    constexpr int TB = 128 * LDS * 2;   // 10240 bytes per tile
    extern __shared__ char smem[];      // A: ci*TB ; W: (4+ci)*TB

    const int tid = threadIdx.x, wid = tid >> 5, lid = tid & 31;
    const int wm = wid & 3, wn = wid >> 2;
    const int g  = lid >> 2, t = lid & 3;
    const int brow = blockIdx.x * 128;

    float acc[2][8][4];
#pragma unroll
    for (int mt = 0; mt < 2; mt++)
#pragma unroll
        for (int nt = 0; nt < 8; nt++)
#pragma unroll
            for (int q = 0; q < 4; q++) acc[mt][nt][q] = 0.f;

#pragma unroll
    for (int ci = 0; ci < 4; ci++) {
        char* Ad = smem + ci*TB;
        char* Wd = smem + (4+ci)*TB;
#pragma unroll
        for (int f = tid; f < 512; f += 256) {
            int row = f >> 2, kq = (f & 3) * 8;
            int gr = brow + row;
            cpa16(smem_u32(Ad + (row*LDS + kq)*2),
                  A + (size_t)gr*HH + ci*32 + kq, (gr < M) ? 16u : 0u);
        }
#pragma unroll
        for (int f = tid; f < 512; f += 256) {
            int n = f >> 2, kq = (f & 3) * 8;
            cpa16(smem_u32(Wd + (n*LDS + kq)*2),
                  W + (size_t)n*HH + ci*32 + kq, 16u);
        }
        COMMITG();
    }

#pragma unroll
    for (int ci = 0; ci < 4; ci++) {
        if      (ci == 0) WAITG(3);
        else if (ci == 1) WAITG(2);
        else if (ci == 2) WAITG(1);
        else              WAITG(0);
        __syncthreads();
        compute_chunk_h(acc, (const __half*)(smem + ci*TB), LDS,
                        (const __half*)(smem + (4+ci)*TB), wm, wn, g, t);
    }

#pragma unroll
    for (int mt = 0; mt < 2; mt++) {
#pragma unroll
        for (int half = 0; half < 2; half++) {
            int row = brow + wm*32 + mt*16 + g + half*8;
            if (row >= M) continue;
            size_t ro = (size_t)row*HH;
            float dsc = g_dis[row];
#pragma unroll
            for (int nt = 0; nt < 8; nt++) {
                int col = wn*64 + nt*8 + t*2;
                *reinterpret_cast<__half2*>(out + ro + col) =
                    __floats2half2_rn(acc[mt][nt][half*2+0]*dsc, acc[mt][nt][half*2+1]*dsc);
            }
        }
    }
}

// ---------------- fused head GEMM (h tile cached in smem) --------------------
// phase 1: t1 = silu(h @ pw1^T + pb1) -> smem (fp16)
// phase 2: acc = h @ W1a^T + t1 @ Wc^T ; hid = silu(acc + c2 + gh[batch]) ;
//          out[row] += hid . w2
__global__ __launch_bounds__(256, 2) void head_gemm_k(
    const float* __restrict__ w2, const int* __restrict__ batch,
    const float* __restrict__ pb1, float* __restrict__ out)
{
    constexpr int LDS = 40, HLD = 136;
    constexpr int TB = 128 * LDS * 2;           // 10240 (W buffer)
    constexpr int HTB = 128 * HLD * 2;          // 34816
    extern __shared__ char smem[];
    __half* Ht  = (__half*)smem;                         // [0, 34816)
    char*   Wb  = smem + HTB;                            // 2 x 10240
    __half* t1s = (__half*)(smem + HTB + 2*TB);          // 34816

    const int tid = threadIdx.x, wid = tid >> 5, lid = tid & 31;
    const int wm = wid & 3, wn = wid >> 2;
    const int g  = lid >> 2, t = lid & 3;
    const int brow = blockIdx.x * 128;

    float acc[2][8][4];
#pragma unroll
    for (int mt = 0; mt < 2; mt++)
#pragma unroll
        for (int nt = 0; nt < 8; nt++)
#pragma unroll
            for (int q = 0; q < 4; q++) acc[mt][nt][q] = 0.f;

#define HW_LOAD(ci, WP, KOFF) do {                                              \
        char* Wd = Wb + ((ci) & 1)*TB;                                          \
        _Pragma("unroll")                                                       \
        for (int f = tid; f < 512; f += 256) {                                  \
            int n = f >> 2, kq = (f & 3) * 8;                                   \
            cpa16(smem_u32(Wd + (n*LDS + kq)*2),                                \
                  (WP) + (size_t)n*HH + (KOFF) + kq, 16u);                      \
        }                                                                       \
        COMMITG();                                                              \
    } while(0)

    // ---- load full h tile once (group 0) ----
#pragma unroll
    for (int f = tid; f < 2048; f += 256) {
        int row = f >> 4, kq = (f & 15) * 8;
        int gr = brow + row;
        cpa16(smem_u32((char*)(Ht + row*HLD + kq)),
              g_h + (size_t)gr*HH + kq, (gr < NN) ? 16u : 0u);
    }
    COMMITG();

    // ---- phase 1: acc = h @ pw1^T ----
    const __half* PW1 = g_wh + HOFF_PW1;
    HW_LOAD(0, PW1, 0);
#pragma unroll
    for (int ci = 0; ci < 4; ci++) {
        if (ci + 1 < 4) { HW_LOAD(ci+1, PW1, (ci+1)*32); WAITG(1); }
        else            { WAITG(0); }
        __syncthreads();
        compute_chunk_h(acc, Ht + ci*32, HLD,
                        (const __half*)(Wb + (ci & 1)*TB), wm, wn, g, t);
        __syncthreads();
    }

    // phase-1 epilogue -> t1s (fp16), then reset acc
#pragma unroll
    for (int mt = 0; mt < 2; mt++)
#pragma unroll
        for (int half = 0; half < 2; half++) {
            int m = wm*32 + mt*16 + g + half*8;
#pragma unroll
            for (int nt = 0; nt < 8; nt++) {
                int col = wn*64 + nt*8 + t*2;
                float v0 = siluf(acc[mt][nt][half*2+0] + pb1[col]);
                float v1 = siluf(acc[mt][nt][half*2+1] + pb1[col+1]);
                *reinterpret_cast<__half2*>(t1s + m*HLD + col) = __floats2half2_rn(v0, v1);
            }
        }
#pragma unroll
    for (int mt = 0; mt < 2; mt++)
#pragma unroll
        for (int nt = 0; nt < 8; nt++)
#pragma unroll
            for (int q = 0; q < 4; q++) acc[mt][nt][q] = 0.f;
    __syncthreads();

    // ---- phase 2: acc = h @ W1a^T + t1 @ Wc^T (K=256) ----
    const __half* W1A = g_wh + HOFF_W1A;
    HW_LOAD(0, W1A, 0);
#pragma unroll
    for (int ci = 0; ci < 8; ci++) {
        if (ci + 1 < 8) {
            if (ci + 1 < 4) HW_LOAD(ci+1, W1A, (ci+1)*32);
            else            HW_LOAD(ci+1, g_wch, ((ci+1) & 3)*32);
            WAITG(1);
        } else WAITG(0);
        __syncthreads();
        const __half* Ap = (ci < 4) ? (Ht + ci*32) : (t1s + (ci-4)*32);
        compute_chunk_h(acc, Ap, HLD,
                        (const __half*)(Wb + (ci & 1)*TB), wm, wn, g, t);
        __syncthreads();
    }
#undef HW_LOAD

    // ---- final epilogue: silu + dot(w2) + red.add ----
#pragma unroll
    for (int mt = 0; mt < 2; mt++) {
#pragma unroll
        for (int half = 0; half < 2; half++) {
            int row = brow + wm*32 + mt*16 + g + half*8;
            float partial = 0.f;
            if (row < NN) {
                const float* ghrow = g_gh + (size_t)batch[row]*HH;
#pragma unroll
                for (int nt = 0; nt < 8; nt++) {
                    int col = wn*64 + nt*8 + t*2;
                    float v0 = siluf(acc[mt][nt][half*2+0] + g_c2[col]   + ghrow[col]);
                    float v1 = siluf(acc[mt][nt][half*2+1] + g_c2[col+1] + ghrow[col+1]);
                    partial = fmaf(v0, w2[col], partial);
                    partial = fmaf(v1, w2[col+1], partial);
                }
            }
            partial += __shfl_xor_sync(0xffffffffu, partial, 1);
            partial += __shfl_xor_sync(0xffffffffu, partial, 2);
            if (t == 0 && row < NN)
                asm volatile("red.global.add.f32 [%0], %1;" :: "l"(out + row), "f"(partial) : "memory");
        }
    }
}

// ---- fused neighbor-gather + silu + LN + residual (+pool) ------------------
template<bool POOL>
__global__ __launch_bounds__(256) void gather_ln_k(const float* __restrict__ bias,
                                                   const float* __restrict__ lng,
                                                   const float* __restrict__ lnb,
                                                   const int* __restrict__ batch)
{
    int node = blockIdx.x * 16 + (threadIdx.x >> 4);
    if (node >= NN) return;
    const int l16 = threadIdx.x & 15;
    const int c0  = l16 * 8;
    const int cnt   = g_deg[node];
    const int start = g_rowptr[node];
    const float di  = g_dis[node];
    const size_t off = (size_t)node*HH + c0;

    float a[8] = {0,0,0,0,0,0,0,0};
    acc8(a, *reinterpret_cast<const uint4*>(g_hw + off));   // self term (already *di)

    for (int base = 0; base < cnt; base += 4) {
        int m = cnt - base;
        int i0 = g_csrc[start + base];
        int i1 = (m > 1) ? g_csrc[start + base + 1] : i0;
        int i2 = (m > 2) ? g_csrc[start + base + 2] : i0;
        int i3 = (m > 3) ? g_csrc[start + base + 3] : i0;
        uint4 u0 = *reinterpret_cast<const uint4*>(g_hw + (size_t)i0*HH + c0);
        uint4 u1 = *reinterpret_cast<const uint4*>(g_hw + (size_t)i1*HH + c0);
        uint4 u2 = *reinterpret_cast<const uint4*>(g_hw + (size_t)i2*HH + c0);
        uint4 u3 = *reinterpret_cast<const uint4*>(g_hw + (size_t)i3*HH + c0);
        acc8(a, u0);
        if (m > 1) acc8(a, u1);
        if (m > 2) acc8(a, u2);
        if (m > 3) acc8(a, u3);
    }

    float4 b0 = ld4(bias + c0), b1 = ld4(bias + c0 + 4);
    float s[8];
    s[0] = siluf(fmaf(a[0], di, b0.x)); s[1] = siluf(fmaf(a[1], di, b0.y));
    s[2] = siluf(fmaf(a[2], di, b0.z)); s[3] = siluf(fmaf(a[3], di, b0.w));
    s[4] = siluf(fmaf(a[4], di, b1.x)); s[5] = siluf(fmaf(a[5], di, b1.y));
    s[6] = siluf(fmaf(a[6], di, b1.z)); s[7] = siluf(fmaf(a[7], di, b1.w));

    float sum = 0.f, sq = 0.f;
#pragma unroll
    for (int q = 0; q < 8; q++) { sum += s[q]; sq = fmaf(s[q], s[q], sq); }
#pragma unroll
    for (int o = 1; o < 16; o <<= 1) {
        sum += __shfl_xor_sync(0xffffffffu, sum, o);
        sq  += __shfl_xor_sync(0xffffffffu, sq,  o);
    }
    float mu  = sum * (1.f/128.f);
    float var = sq * (1.f/128.f) - mu*mu;
    float inv = rsqrtf(var + 1e-5f);

    float4 g0 = ld4(lng + c0), g1 = ld4(lng + c0 + 4);
    float4 e0 = ld4(lnb + c0), e1 = ld4(lnb + c0 + 4);
    float hv[8];
    unp8(hv, *reinterpret_cast<const uint4*>(g_h + off));
    hv[0] += (s[0]-mu)*inv*g0.x + e0.x;
    hv[1] += (s[1]-mu)*inv*g0.y + e0.y;
    hv[2] += (s[2]-mu)*inv*g0.z + e0.z;
    hv[3] += (s[3]-mu)*inv*g0.w + e0.w;
    hv[4] += (s[4]-mu)*inv*g1.x + e1.x;
    hv[5] += (s[5]-mu)*inv*g1.y + e1.y;
    hv[6] += (s[6]-mu)*inv*g1.z + e1.z;
    hv[7] += (s[7]-mu)*inv*g1.w + e1.w;
    *reinterpret_cast<uint4*>(g_h + off) = pk8(hv);

    if (POOL) {
        int b = batch[node];
        float* p = g_gsum + (size_t)b*HH + c0;
        asm volatile("red.global.add.v4.f32 [%0], {%1,%2,%3,%4};"
                     :: "l"(p), "f"(hv[0]), "f"(hv[1]), "f"(hv[2]), "f"(hv[3]) : "memory");
        asm volatile("red.global.add.v4.f32 [%0], {%1,%2,%3,%4};"
                     :: "l"(p+4), "f"(hv[4]), "f"(hv[5]), "f"(hv[6]), "f"(hv[7]) : "memory");
        if (l16 == 0) atomicAdd(&g_cnt[b], 1.0f);
    }
}

// ---------------- launch ----------------
extern "C" void kernel_launch(void* const* d_in, const int* in_sizes, int n_in,
                              void* d_out, int out_size)
{
    const float* x      = (const float*)d_in[0];
    const int*   ei     = (const int*)  d_in[1];
    const int*   src    = ei;
    const int*   dst    = ei + EE;
    const int*   batch  = (const int*)  d_in[2];
    const float* in_w   = (const float*)d_in[3];
    const float* in_b   = (const float*)d_in[4];
    const float* conv_w = (const float*)d_in[5];
    const float* conv_b = (const float*)d_in[6];
    const float* ln_g   = (const float*)d_in[7];
    const float* ln_b   = (const float*)d_in[8];
    const float* pw1    = (const float*)d_in[9];
    const float* pb1    = (const float*)d_in[10];
    const float* pw2    = (const float*)d_in[11];
    const float* pb2    = (const float*)d_in[12];
    const float* hw1    = (const float*)d_in[13];
    const float* hb1    = (const float*)d_in[14];
    const float* hw2    = (const float*)d_in[15];
    const float* hb2    = (const float*)d_in[16];
    float* out = (float*)d_out;

    float *p_gsum, *p_gh, *p_wr;
    __half *p_h, *p_hw, *p_wh, *p_wch;
    cudaGetSymbolAddress((void**)&p_h,    g_h);
    cudaGetSymbolAddress((void**)&p_hw,   g_hw);
    cudaGetSymbolAddress((void**)&p_gsum, g_gsum);
    cudaGetSymbolAddress((void**)&p_gh,   g_gh);
    cudaGetSymbolAddress((void**)&p_wr,   g_wr);
    cudaGetSymbolAddress((void**)&p_wh,   g_wh);
    cudaGetSymbolAddress((void**)&p_wch,  g_wch);

    static cudaStream_t s_csr = nullptr, s_wp = nullptr, s_wc = nullptr;
    static cudaEvent_t  ev_fork = nullptr, ev_csr = nullptr, ev_wp = nullptr,
                        ev_prep = nullptr, ev_wc = nullptr;
    if (s_csr == nullptr) {
        cudaStreamCreateWithFlags(&s_csr, cudaStreamNonBlocking);
        cudaStreamCreateWithFlags(&s_wp,  cudaStreamNonBlocking);
        cudaStreamCreateWithFlags(&s_wc,  cudaStreamNonBlocking);
        cudaEventCreateWithFlags(&ev_fork, cudaEventDisableTiming);
        cudaEventCreateWithFlags(&ev_csr,  cudaEventDisableTiming);
        cudaEventCreateWithFlags(&ev_wp,   cudaEventDisableTiming);
        cudaEventCreateWithFlags(&ev_prep, cudaEventDisableTiming);
        cudaEventCreateWithFlags(&ev_wc,   cudaEventDisableTiming);
    }

    const int TPB = 256;
    const int gI  = (GG*HH + TPB - 1) / TPB;     // covers NN too
    const int gN  = (NN + TPB - 1) / TPB;
    const int gE  = (EE + TPB - 1) / TPB;
    const int gG16 = (NN + 15) / 16;
    const int gGm = (NN + 127) / 128;
    const int gGg = GG / 128;
    const int gW  = (139264 + TPB - 1) / TPB;

    const int SMB_F    = 4 * 128 * 36 * 4;        // 73728 (tf32 GEMM)
    const int SMB_CONV = 8 * 128 * 40 * 2;        // 81920 (full-prefetch fp16 GEMM)
    const int SMB_HEAD = 128*136*2 + 2*128*40*2 + 128*136*2;  // 90112
    cudaFuncSetAttribute(mma_gemm_k< 64,0,true ,true >, cudaFuncAttributeMaxDynamicSharedMemorySize, SMB_F);
    cudaFuncSetAttribute(mma_gemm_k<128,0,true ,false>, cudaFuncAttributeMaxDynamicSharedMemorySize, SMB_F);
    cudaFuncSetAttribute(mma_gemm_k<128,3,false,true >, cudaFuncAttributeMaxDynamicSharedMemorySize, SMB_F);
    cudaFuncSetAttribute(conv_gemm_k, cudaFuncAttributeMaxDynamicSharedMemorySize, SMB_CONV);
    cudaFuncSetAttribute(head_gemm_k, cudaFuncAttributeMaxDynamicSharedMemorySize, SMB_HEAD);

    // ---- init, then fork: CSR chain || weight-prep + in-proj || c2 + Wc ----
    init_k<<<gI, TPB>>>(out, hb2);
    cudaEventRecord(ev_fork, 0);
    cudaStreamWaitEvent(s_csr, ev_fork, 0);
    cudaStreamWaitEvent(s_wp,  ev_fork, 0);
    cudaStreamWaitEvent(s_wc,  ev_fork, 0);

    csr_hist_k <<<gE, TPB, 0, s_csr>>>(dst);
    csr_scan1_k<<<NB, TPB, 0, s_csr>>>();
    csr_scan2_k<<<1,  TPB, 0, s_csr>>>();
    csr_scan3_k<<<gN, TPB, 0, s_csr>>>();
    csr_fill_k <<<gE, TPB, 0, s_csr>>>(src, dst);
    cudaEventRecord(ev_csr, s_csr);

    prep_w_k<<<gW, TPB, 0, s_wp>>>(in_w, conv_w, pw1, hw1, pw2);
    cudaEventRecord(ev_prep, s_wp);
    // in-proj: h = x @ in_w^T + in_b -> fp16
    mma_gemm_k<64,0,true,true><<<gGm, TPB, SMB_F, s_wp>>>(
        x, 64, p_wr + WOFF_INW, 64, in_b, p_h, NN);
    cudaEventRecord(ev_wp, s_wp);

    c2_k<<<1, 128, 0, s_wc>>>(hw1, pb2, hb1);
    cudaStreamWaitEvent(s_wc, ev_prep, 0);
    // Wc = W1a_h @ pw2 -> fp16 (concurrent with in-proj)
    mma_gemm_k<128,0,true,false><<<1, TPB, SMB_F, s_wc>>>(
        p_wr + WOFF_HW1, 256, p_wr + WOFF_PW2T, 128, nullptr, p_wch, 128);
    cudaEventRecord(ev_wc, s_wc);

    cudaStreamWaitEvent(0, ev_csr, 0);
    cudaStreamWaitEvent(0, ev_wp, 0);
    cudaStreamWaitEvent(0, ev_wc, 0);

    // ---- GCN layers (fp16 MMA conv + fused gather) ----
    for (int l = 0; l < 4; l++) {
        conv_gemm_k<<<gGm, TPB, SMB_CONV>>>(p_h, p_wh + HOFF_CONV + (size_t)l*HH*HH, p_hw, NN);
        if (l < 3) gather_ln_k<false><<<gG16, TPB>>>(conv_b + l*HH, ln_g + l*HH, ln_b + l*HH, batch);
        else       gather_ln_k<true ><<<gG16, TPB>>>(conv_b + l*HH, ln_g + l*HH, ln_b + l*HH, batch);
    }

    // gh = (gsum/cnt) @ W1b^T
    mma_gemm_k<128,3,false,true><<<gGg, TPB, SMB_F>>>(
        p_gsum, 128, p_wr + WOFF_HW1 + 128, 256, nullptr, p_gh, GG);

    // fused head (h tile cached in smem)
    head_gemm_k<<<gGm, TPB, SMB_HEAD>>>(hw2, batch, pb1, out);
}